// round 1
// baseline (speedup 1.0000x reference)
#include <cuda_runtime.h>
#include <math_constants.h>

#define BATCH  2
#define COILS  16
#define NIM    256
#define KG     512          // oversampled grid per dim
#define JW     6
#define TCENTER 3072
#define TLEN   6145
#define MPTS   409600

// Scratch: row-FFT output (B,C,256,512) and transposed grid (B, 512*512, C)
static __device__ __align__(256) float2 g_Gr[(size_t)BATCH*COILS*NIM*KG];
static __device__ __align__(256) float2 g_Gft[(size_t)BATCH*KG*KG*COILS];

__device__ __forceinline__ float2 cmulf(float2 a, float2 b) {
    return make_float2(a.x*b.x - a.y*b.y, a.x*b.y + a.y*b.x);
}

// In: sA[0..511] natural order. Out: sB[0..511] = forward unnormalized DFT.
// 256 threads, t in [0,256).
__device__ __forceinline__ void fft512_body(float2* sA, float2* sB, int t) {
    __syncthreads();
    sB[t]       = sA[__brev(t) >> 23];
    sB[t + 256] = sA[__brev(t + 256) >> 23];
    __syncthreads();
#pragma unroll
    for (int half = 1; half <= 256; half <<= 1) {
        int k  = t & (half - 1);
        int i0 = 2 * t - k;
        int i1 = i0 + half;
        float ang = -CUDART_PI_F * (float)k / (float)half;
        float sw, cw;
        sincosf(ang, &sw, &cw);
        float2 u = sB[i0];
        float2 v = cmulf(sB[i1], make_float2(cw, sw));
        sB[i0] = make_float2(u.x + v.x, u.y + v.y);
        sB[i1] = make_float2(u.x - v.x, u.y - v.y);
        __syncthreads();
    }
}

// Pass 1: apodize + row FFT. grid (256 rows, B*C), 256 threads.
__global__ __launch_bounds__(256) void pass1_rowfft(const float* __restrict__ x,
                                                    const float* __restrict__ sc) {
    __shared__ float2 sA[512];
    __shared__ float2 sB[512];
    int r  = blockIdx.x;      // image row 0..255
    int bc = blockIdx.y;      // b*C + c
    int t  = threadIdx.x;

    const float* xr  = x  + ((size_t)bc * 2 + 0) * (NIM * NIM) + (size_t)r * NIM;
    const float* xi  = x  + ((size_t)bc * 2 + 1) * (NIM * NIM) + (size_t)r * NIM;
    const float* scr = sc + (size_t)r * NIM;
    const float* sci = sc + (size_t)NIM * NIM + (size_t)r * NIM;

    float a = xr[t], b = xi[t], cr = scr[t], ci = sci[t];
    sA[t]       = make_float2(a * cr - b * ci, a * ci + b * cr);
    sA[t + 256] = make_float2(0.f, 0.f);

    fft512_body(sA, sB, t);

    float2* out = g_Gr + ((size_t)bc * NIM + r) * KG;
    out[t]       = sB[t];
    out[t + 256] = sB[t + 256];
}

// Pass 2: column FFT + transposed (coil-innermost) store. grid (512 cols, B*C).
__global__ __launch_bounds__(256) void pass2_colfft() {
    __shared__ float2 sA[512];
    __shared__ float2 sB[512];
    int col = blockIdx.x;     // 0..511
    int bc  = blockIdx.y;     // b*C + c
    int b   = bc >> 4;
    int c   = bc & 15;
    int t   = threadIdx.x;

    const float2* in = g_Gr + (size_t)bc * NIM * KG + col;
    sA[t]       = in[(size_t)t * KG];
    sA[t + 256] = make_float2(0.f, 0.f);

    fft512_body(sA, sB, t);

    // Gft[b][r*512+col][c]
    float2* out = g_Gft + (size_t)b * KG * KG * COILS + c;
    out[((size_t)t * KG + col) * COILS]         = sB[t];
    out[((size_t)(t + 256) * KG + col) * COILS] = sB[t + 256];
}

// Interpolation: 16 k-space points x 16 coils per block (256 threads).
// grid (M/16, B).
__global__ __launch_bounds__(256) void interp_kernel(const float* __restrict__ om,
                                                     const float* __restrict__ tab0,
                                                     const float* __restrict__ tab1,
                                                     const float* __restrict__ nshift,
                                                     float* __restrict__ out) {
    __shared__ float2 sc0[16][JW];
    __shared__ float2 sc1[16][JW];
    __shared__ int    si0[16][JW];   // premultiplied row*KG
    __shared__ int    si1[16][JW];
    __shared__ float2 sph[16];
    __shared__ float  sout[2][16][16];   // [reim][coil][m_local]

    int b  = blockIdx.y;
    int m0 = blockIdx.x * 16;
    int t  = threadIdx.x;

    if (t < 16) {
        int m = m0 + t;
        float om0 = om[((size_t)b * 2 + 0) * MPTS + m];
        float om1 = om[((size_t)b * 2 + 1) * MPTS + m];
        const float S = (float)(KG / (2.0 * 3.14159265358979323846));
        float tm0 = om0 * S;
        float tm1 = om1 * S;
        int koff0 = (int)floorf(tm0 - 3.0f) + 1;
        int koff1 = (int)floorf(tm1 - 3.0f) + 1;
#pragma unroll
        for (int j = 0; j < JW; j++) {
            int g0   = koff0 + j;
            int idx0 = __float2int_rn((tm0 - (float)g0) * 1024.0f) + TCENTER;
            sc0[t][j] = make_float2(tab0[idx0], tab0[TLEN + idx0]);
            si0[t][j] = (g0 & (KG - 1)) * KG;
            int g1   = koff1 + j;
            int idx1 = __float2int_rn((tm1 - (float)g1) * 1024.0f) + TCENTER;
            sc1[t][j] = make_float2(tab1[idx1], tab1[TLEN + idx1]);
            si1[t][j] = g1 & (KG - 1);
        }
        float ph = om0 * nshift[0] + om1 * nshift[1];
        float sp, cp;
        sincosf(ph, &sp, &cp);
        sph[t] = make_float2(cp, sp);
    }
    __syncthreads();

    int ml = t >> 4;      // local point index
    int c  = t & 15;      // coil
    const float2* G = g_Gft + (size_t)b * KG * KG * COILS + c;

    float2 acc = make_float2(0.f, 0.f);
#pragma unroll
    for (int a = 0; a < JW; a++) {
        int    rowoff = si0[ml][a];
        float2 ca     = sc0[ml][a];
#pragma unroll
        for (int bb = 0; bb < JW; bb++) {
            float2 coef = cmulf(ca, sc1[ml][bb]);
            float2 v    = G[(size_t)(rowoff + si1[ml][bb]) * COILS];
            acc.x += coef.x * v.x - coef.y * v.y;
            acc.y += coef.x * v.y + coef.y * v.x;
        }
    }
    float2 p = sph[ml];
    float2 r = cmulf(acc, p);
    sout[0][c][ml] = r.x;
    sout[1][c][ml] = r.y;
    __syncthreads();

    // coalesced store: thread -> (coil = t>>4, m_local = t&15)
    int cc = t >> 4;
    int mm = t & 15;
    size_t base = ((size_t)(b * COILS + cc) * 2) * MPTS + m0 + mm;
    out[base]        = sout[0][cc][mm];
    out[base + MPTS] = sout[1][cc][mm];
}

extern "C" void kernel_launch(void* const* d_in, const int* in_sizes, int n_in,
                              void* d_out, int out_size) {
    (void)in_sizes; (void)n_in; (void)out_size;
    const float* x      = (const float*)d_in[0];   // (B,C,2,256,256)
    const float* om     = (const float*)d_in[1];   // (B,2,M)
    const float* sc     = (const float*)d_in[2];   // (2,256,256)
    const float* tab0   = (const float*)d_in[3];   // (2,6145)
    const float* tab1   = (const float*)d_in[4];   // (2,6145)
    const float* nshift = (const float*)d_in[5];   // (2,)
    float* out          = (float*)d_out;           // (B,C,2,M)

    dim3 g1(NIM, BATCH * COILS);
    pass1_rowfft<<<g1, 256>>>(x, sc);

    dim3 g2(KG, BATCH * COILS);
    pass2_colfft<<<g2, 256>>>();

    dim3 g3(MPTS / 16, BATCH);
    interp_kernel<<<g3, 256>>>(om, tab0, tab1, nshift, out);
}

// round 4
// speedup vs baseline: 1.4180x; 1.4180x over previous
#include <cuda_runtime.h>
#include <cuda_fp16.h>
#include <math_constants.h>

#define BATCH  2
#define COILS  16
#define NIM    256
#define KG     512
#define JW     6
#define TCENTER 3072
#define TLEN   6145
#define MPTS   409600
#define GSCALE   0x1p-34f
#define GSCALE_I 0x1p34f

// Scratch: row-FFT output (B,C,256,512) fp32 and transposed grid (B,512*512,C) fp16
static __device__ __align__(256) float2  g_Gr[(size_t)BATCH*COILS*NIM*KG];
static __device__ __align__(256) __half2 g_Gft[(size_t)BATCH*KG*KG*COILS];

__device__ __forceinline__ float2 cmulf(float2 a, float2 b) {
    return make_float2(a.x*b.x - a.y*b.y, a.x*b.y + a.y*b.x);
}

__device__ __forceinline__ float clampq(float v) {
    return fminf(fmaxf(v, -60000.0f), 60000.0f);
}

// ---------------------------------------------------------------------------
// Pass 1: apodize + row FFT (512-pt, 256 nonzero inputs). grid(256, B*C), 256 thr.
// ---------------------------------------------------------------------------
__global__ __launch_bounds__(256) void pass1_rowfft(const float* __restrict__ x,
                                                    const float* __restrict__ sc) {
    __shared__ float2 sA[512];
    __shared__ float2 sB[512];
    __shared__ float2 tw[256];
    int r  = blockIdx.x;
    int bc = blockIdx.y;
    int t  = threadIdx.x;

    { // twiddle table: tw[j] = exp(-i*pi*j/256)
        float ang = -CUDART_PI_F * (float)t / 256.0f;
        float s, c; sincosf(ang, &s, &c);
        tw[t] = make_float2(c, s);
    }

    const float* xr  = x  + ((size_t)bc * 2 + 0) * (NIM * NIM) + (size_t)r * NIM;
    const float* xi  = x  + ((size_t)bc * 2 + 1) * (NIM * NIM) + (size_t)r * NIM;
    const float* scr = sc + (size_t)r * NIM;
    const float* sci = sc + (size_t)NIM * NIM + (size_t)r * NIM;

    float a = xr[t], b = xi[t], cr = scr[t], ci = sci[t];
    sA[t]       = make_float2(a * cr - b * ci, a * ci + b * cr);
    sA[t + 256] = make_float2(0.f, 0.f);
    __syncthreads();

    sB[t]       = sA[__brev(t) >> 23];
    sB[t + 256] = sA[__brev(t + 256) >> 23];
    __syncthreads();

#pragma unroll
    for (int s = 0; s <= 8; s++) {
        int half = 1 << s;
        int k  = t & (half - 1);
        int i0 = 2 * t - k;
        int i1 = i0 + half;
        float2 w = tw[k << (8 - s)];
        float2 u = sB[i0];
        float2 v = cmulf(sB[i1], w);
        sB[i0] = make_float2(u.x + v.x, u.y + v.y);
        sB[i1] = make_float2(u.x - v.x, u.y - v.y);
        __syncthreads();
    }

    float2* out = g_Gr + ((size_t)bc * NIM + r) * KG;
    out[t]       = sB[t];
    out[t + 256] = sB[t + 256];
}

// ---------------------------------------------------------------------------
// Pass 2: column FFT, 4 columns per block (full 32B sector reads), fp16 store.
// grid(KG/4, B*C), 256 threads.
// ---------------------------------------------------------------------------
__global__ __launch_bounds__(256) void pass2_colfft() {
    __shared__ float2 sA[4][512];
    __shared__ float2 sB[4][512];
    __shared__ float2 tw[256];
    int col0 = blockIdx.x * 4;
    int bc   = blockIdx.y;
    int b    = bc >> 4;
    int c    = bc & 15;
    int t    = threadIdx.x;

    {
        float ang = -CUDART_PI_F * (float)t / 256.0f;
        float s, cc; sincosf(ang, &s, &cc);
        tw[t] = make_float2(cc, s);
    }

    const float2* in = g_Gr + (size_t)bc * NIM * KG;
#pragma unroll
    for (int i = 0; i < 4; i++) {
        int e  = t + 256 * i;       // 1024 = 256 rows x 4 cols
        int r  = e >> 2;
        int cc = e & 3;
        sA[cc][r] = in[(size_t)r * KG + col0 + cc];
    }
#pragma unroll
    for (int cc = 0; cc < 4; cc++) sA[cc][t + 256] = make_float2(0.f, 0.f);
    __syncthreads();

    int j0 = __brev(t) >> 23;
    int j1 = __brev(t + 256) >> 23;
#pragma unroll
    for (int cc = 0; cc < 4; cc++) {
        sB[cc][t]       = sA[cc][j0];
        sB[cc][t + 256] = sA[cc][j1];
    }
    __syncthreads();

#pragma unroll
    for (int s = 0; s <= 8; s++) {
        int half = 1 << s;
        int k  = t & (half - 1);
        int i0 = 2 * t - k;
        int i1 = i0 + half;
        float2 w = tw[k << (8 - s)];
#pragma unroll
        for (int cc = 0; cc < 4; cc++) {
            float2 u = sB[cc][i0];
            float2 v = cmulf(sB[cc][i1], w);
            sB[cc][i0] = make_float2(u.x + v.x, u.y + v.y);
            sB[cc][i1] = make_float2(u.x - v.x, u.y - v.y);
        }
        __syncthreads();
    }

    // Gft[b][row*512+col][coil] as scaled half2
    __half2* out = g_Gft + (size_t)b * KG * KG * COILS + c;
#pragma unroll
    for (int half_i = 0; half_i < 2; half_i++) {
        int row = t + half_i * 256;
#pragma unroll
        for (int cc = 0; cc < 4; cc++) {
            float2 v = sB[cc][row];
            out[((size_t)row * KG + col0 + cc) * COILS] =
                __floats2half2_rn(clampq(v.x * GSCALE), clampq(v.y * GSCALE));
        }
    }
}

// ---------------------------------------------------------------------------
// Interpolation: 64 points x 4 threads (4 coils each) per block. grid(M/64, B).
// ---------------------------------------------------------------------------
#define PB 64
__global__ __launch_bounds__(256) void interp_kernel(const float* __restrict__ om,
                                                     const float* __restrict__ tab0,
                                                     const float* __restrict__ tab1,
                                                     const float* __restrict__ nshift,
                                                     float* __restrict__ out) {
    __shared__ int    soff[PB][36];
    __shared__ float2 scoef[PB][36];
    __shared__ float2 sc0[PB][JW];
    __shared__ float2 sc1[PB][JW];
    __shared__ int    si0[PB][JW];
    __shared__ int    si1[PB][JW];
    __shared__ float2 sph[PB];
    __shared__ float  sout[32 * PB];   // [c*2+comp][p]

    int b  = blockIdx.y;
    int m0 = blockIdx.x * PB;
    int t  = threadIdx.x;

    if (t < PB) {
        int m = m0 + t;
        float om0 = om[((size_t)b * 2 + 0) * MPTS + m];
        float om1 = om[((size_t)b * 2 + 1) * MPTS + m];
        const float S = (float)(KG / (2.0 * 3.14159265358979323846));
        float tm0 = om0 * S;
        float tm1 = om1 * S;
        int koff0 = (int)floorf(tm0 - 3.0f) + 1;
        int koff1 = (int)floorf(tm1 - 3.0f) + 1;
#pragma unroll
        for (int j = 0; j < JW; j++) {
            int g0   = koff0 + j;
            int idx0 = __float2int_rn((tm0 - (float)g0) * 1024.0f) + TCENTER;
            sc0[t][j] = make_float2(tab0[idx0], tab0[TLEN + idx0]);
            si0[t][j] = (g0 & (KG - 1)) * KG;
            int g1   = koff1 + j;
            int idx1 = __float2int_rn((tm1 - (float)g1) * 1024.0f) + TCENTER;
            sc1[t][j] = make_float2(tab1[idx1], tab1[TLEN + idx1]);
            si1[t][j] = g1 & (KG - 1);
        }
        float ph = om0 * nshift[0] + om1 * nshift[1];
        float sp, cp;
        sincosf(ph, &sp, &cp);
        sph[t] = make_float2(cp * GSCALE_I, sp * GSCALE_I);
    }
    __syncthreads();

    // fused 36 coefficients + element offsets per point
    for (int n = t; n < PB * 36; n += 256) {
        int p  = n / 36;
        int q  = n - p * 36;
        int a  = q / 6;
        int bb = q - a * 6;
        scoef[p][q] = cmulf(sc0[p][a], sc1[p][bb]);
        soff[p][q]  = (si0[p][a] + si1[p][bb]) * COILS;
    }
    __syncthreads();

    int p  = t >> 2;
    int q4 = (t & 3) * 4;   // coil base (4 coils per thread)
    const __half2* G = g_Gft + (size_t)b * KG * KG * COILS + q4;

    float2 a0 = make_float2(0.f, 0.f), a1 = a0, a2 = a0, a3 = a0;
#pragma unroll 6
    for (int n = 0; n < 36; n++) {
        int    off = soff[p][n];
        float2 cf  = scoef[p][n];
        float4 raw = *reinterpret_cast<const float4*>(G + off);
        __half2 h0 = *reinterpret_cast<__half2*>(&raw.x);
        __half2 h1 = *reinterpret_cast<__half2*>(&raw.y);
        __half2 h2 = *reinterpret_cast<__half2*>(&raw.z);
        __half2 h3 = *reinterpret_cast<__half2*>(&raw.w);
        float2 v0 = __half22float2(h0);
        float2 v1 = __half22float2(h1);
        float2 v2 = __half22float2(h2);
        float2 v3 = __half22float2(h3);
        a0.x += cf.x * v0.x - cf.y * v0.y;  a0.y += cf.x * v0.y + cf.y * v0.x;
        a1.x += cf.x * v1.x - cf.y * v1.y;  a1.y += cf.x * v1.y + cf.y * v1.x;
        a2.x += cf.x * v2.x - cf.y * v2.y;  a2.y += cf.x * v2.y + cf.y * v2.x;
        a3.x += cf.x * v3.x - cf.y * v3.y;  a3.y += cf.x * v3.y + cf.y * v3.x;
    }
    float2 ph = sph[p];
    float2 r0 = cmulf(a0, ph);
    float2 r1 = cmulf(a1, ph);
    float2 r2 = cmulf(a2, ph);
    float2 r3 = cmulf(a3, ph);

    sout[((q4 + 0) * 2 + 0) * PB + p] = r0.x;  sout[((q4 + 0) * 2 + 1) * PB + p] = r0.y;
    sout[((q4 + 1) * 2 + 0) * PB + p] = r1.x;  sout[((q4 + 1) * 2 + 1) * PB + p] = r1.y;
    sout[((q4 + 2) * 2 + 0) * PB + p] = r2.x;  sout[((q4 + 2) * 2 + 1) * PB + p] = r2.y;
    sout[((q4 + 3) * 2 + 0) * PB + p] = r3.x;  sout[((q4 + 3) * 2 + 1) * PB + p] = r3.y;
    __syncthreads();

    float* outp = out + (size_t)b * 2 * COILS * MPTS + m0;
#pragma unroll
    for (int i = 0; i < 8; i++) {
        int idx = i * 256 + t;
        int cr  = idx >> 6;       // c*2+comp
        int m   = idx & 63;
        outp[(size_t)cr * MPTS + m] = sout[idx];
    }
}

extern "C" void kernel_launch(void* const* d_in, const int* in_sizes, int n_in,
                              void* d_out, int out_size) {
    (void)in_sizes; (void)n_in; (void)out_size;
    const float* x      = (const float*)d_in[0];
    const float* om     = (const float*)d_in[1];
    const float* sc     = (const float*)d_in[2];
    const float* tab0   = (const float*)d_in[3];
    const float* tab1   = (const float*)d_in[4];
    const float* nshift = (const float*)d_in[5];
    float* out          = (float*)d_out;

    dim3 g1(NIM, BATCH * COILS);
    pass1_rowfft<<<g1, 256>>>(x, sc);

    dim3 g2(KG / 4, BATCH * COILS);
    pass2_colfft<<<g2, 256>>>();

    dim3 g3(MPTS / PB, BATCH);
    interp_kernel<<<g3, 256>>>(om, tab0, tab1, nshift, out);
}

// round 5
// speedup vs baseline: 1.6177x; 1.1408x over previous
#include <cuda_runtime.h>
#include <cuda_fp16.h>
#include <math_constants.h>

#define BATCH  2
#define COILS  16
#define NIM    256
#define KG     512
#define JW     6
#define TCENTER 3072
#define TLEN   6145
#define MPTS   409600
#define GSCALE   0x1p-34f
#define GSCALE_I 0x1p34f

#define PADI(i) ((i) + ((i) >> 5))   // bank-conflict padding; max 511 -> 526
#define FFTBUF 528

// Scratch: row-FFT output (B,C,256,512) fp32 and transposed grid (B,512*512,C) fp16
static __device__ __align__(256) float2  g_Gr[(size_t)BATCH*COILS*NIM*KG];
static __device__ __align__(256) __half2 g_Gft[(size_t)BATCH*KG*KG*COILS];

__device__ __forceinline__ float2 cmulf(float2 a, float2 b) {
    return make_float2(a.x*b.x - a.y*b.y, a.x*b.y + a.y*b.x);
}

__device__ __forceinline__ float clampq(float v) {
    return fminf(fmaxf(v, -60000.0f), 60000.0f);
}

// 512-pt DIT FFT, 128 threads (tt in [0,128)), data pre-scattered to
// PADI(brev9(n)). 4 fused radix-4 stages + 1 radix-2 stage.
// tw[j] = exp(-i*pi*j/256). Caller must __syncthreads() before entry.
__device__ __forceinline__ void fft512_core(float* re, float* im,
                                            const float2* tw, int tt) {
#pragma unroll
    for (int h = 1; h <= 64; h *= 4) {
        int k    = tt & (h - 1);
        int base = 4 * tt - 3 * k;
        int i0 = PADI(base);
        int i1 = PADI(base + h);
        int i2 = PADI(base + 2 * h);
        int i3 = PADI(base + 3 * h);
        float ar = re[i0], ai = im[i0];
        float br = re[i1], bi = im[i1];
        float cr = re[i2], ci = im[i2];
        float dr = re[i3], di = im[i3];
        float2 w  = tw[k * (256 / h)];   // exp(-i*pi*k/h)
        float2 w1 = tw[k * (128 / h)];   // exp(-i*pi*k/(2h))
        // stage s (half = h)
        float t1r = w.x * br - w.y * bi, t1i = w.x * bi + w.y * br;
        float t2r = w.x * dr - w.y * di, t2i = w.x * di + w.y * dr;
        float Ar = ar + t1r, Ai = ai + t1i;
        float Br = ar - t1r, Bi = ai - t1i;
        float Cr = cr + t2r, Ci = ci + t2i;
        float Dr = cr - t2r, Di = ci - t2i;
        // stage s+1 (half = 2h); w2 = -i*w1
        float ur = w1.x * Cr - w1.y * Ci, ui = w1.x * Ci + w1.y * Cr;
        float vr = w1.y * Dr + w1.x * Di, vi = w1.y * Di - w1.x * Dr;
        re[i0] = Ar + ur;  im[i0] = Ai + ui;
        re[i2] = Ar - ur;  im[i2] = Ai - ui;
        re[i1] = Br + vr;  im[i1] = Bi + vi;
        re[i3] = Br - vr;  im[i3] = Bi - vi;
        __syncthreads();
    }
    // final radix-2 stage, half = 256
#pragma unroll
    for (int j = 0; j < 2; j++) {
        int i  = tt + 128 * j;
        int i0 = PADI(i);
        int i1 = PADI(i + 256);
        float2 w = tw[i];
        float ar = re[i0], ai = im[i0];
        float br = re[i1], bi = im[i1];
        float tr = w.x * br - w.y * bi, ti = w.x * bi + w.y * br;
        re[i0] = ar + tr;  im[i0] = ai + ti;
        re[i1] = ar - tr;  im[i1] = ai - ti;
    }
    __syncthreads();
}

// ---------------------------------------------------------------------------
// Pass 1: apodize + row FFT. 2 rows per 256-thread block. grid(128, B*C).
// ---------------------------------------------------------------------------
__global__ __launch_bounds__(256) void pass1_rowfft(const float* __restrict__ x,
                                                    const float* __restrict__ sc) {
    __shared__ float  s_re[2][FFTBUF];
    __shared__ float  s_im[2][FFTBUF];
    __shared__ float2 tw[256];
    int tid = threadIdx.x;
    int f   = tid >> 7;
    int tt  = tid & 127;
    int r   = blockIdx.x * 2 + f;
    int bc  = blockIdx.y;

    {
        float ang = -CUDART_PI_F * (float)tid / 256.0f;
        float s, c; sincosf(ang, &s, &c);
        tw[tid] = make_float2(c, s);
    }

    float* re = s_re[f];
    float* im = s_im[f];

    const float* xr  = x  + ((size_t)bc * 2 + 0) * (NIM * NIM) + (size_t)r * NIM;
    const float* xi  = x  + ((size_t)bc * 2 + 1) * (NIM * NIM) + (size_t)r * NIM;
    const float* scr = sc + (size_t)r * NIM;
    const float* sci = sc + (size_t)NIM * NIM + (size_t)r * NIM;

#pragma unroll
    for (int j = 0; j < 2; j++) {
        int n = tt + 128 * j;
        float a = xr[n], b = xi[n], cr = scr[n], ci = sci[n];
        int d = PADI(__brev(n) >> 23);
        re[d] = a * cr - b * ci;
        im[d] = a * ci + b * cr;
    }
#pragma unroll
    for (int j = 2; j < 4; j++) {
        int n = tt + 128 * j;
        int d = PADI(__brev(n) >> 23);
        re[d] = 0.f;
        im[d] = 0.f;
    }
    __syncthreads();

    fft512_core(re, im, tw, tt);

    float2* out = g_Gr + ((size_t)bc * NIM + r) * KG;
#pragma unroll
    for (int j = 0; j < 4; j++) {
        int n = tt + 128 * j;
        int d = PADI(n);
        out[n] = make_float2(re[d], im[d]);
    }
}

// ---------------------------------------------------------------------------
// Pass 2: column FFT + fp16 coil-innermost store. 4 cols per 512-thread block.
// grid(128, B*C).
// ---------------------------------------------------------------------------
__global__ __launch_bounds__(512) void pass2_colfft() {
    __shared__ float  s_re[4][FFTBUF];
    __shared__ float  s_im[4][FFTBUF];
    __shared__ float2 tw[256];
    int tid = threadIdx.x;
    int f   = tid >> 7;
    int tt  = tid & 127;
    int col = blockIdx.x * 4 + f;
    int bc  = blockIdx.y;
    int b   = bc >> 4;
    int c   = bc & 15;

    if (tid < 256) {
        float ang = -CUDART_PI_F * (float)tid / 256.0f;
        float s, cc; sincosf(ang, &s, &cc);
        tw[tid] = make_float2(cc, s);
    }

    float* re = s_re[f];
    float* im = s_im[f];

    const float2* in = g_Gr + (size_t)bc * NIM * KG + col;
#pragma unroll
    for (int j = 0; j < 2; j++) {
        int n = tt + 128 * j;
        float2 v = in[(size_t)n * KG];
        int d = PADI(__brev(n) >> 23);
        re[d] = v.x;
        im[d] = v.y;
    }
#pragma unroll
    for (int j = 2; j < 4; j++) {
        int n = tt + 128 * j;
        int d = PADI(__brev(n) >> 23);
        re[d] = 0.f;
        im[d] = 0.f;
    }
    __syncthreads();

    fft512_core(re, im, tw, tt);

    __half2* out = g_Gft + (size_t)b * KG * KG * COILS + c;
#pragma unroll
    for (int j = 0; j < 4; j++) {
        int n = tt + 128 * j;
        int d = PADI(n);
        out[((size_t)n * KG + col) * COILS] =
            __floats2half2_rn(clampq(re[d] * GSCALE), clampq(im[d] * GSCALE));
    }
}

// ---------------------------------------------------------------------------
// Interpolation: 64 points x 4 threads (4 coils each) per block. grid(M/64, B).
// ---------------------------------------------------------------------------
#define PB 64
__global__ __launch_bounds__(256) void interp_kernel(const float* __restrict__ om,
                                                     const float* __restrict__ tab0,
                                                     const float* __restrict__ tab1,
                                                     const float* __restrict__ nshift,
                                                     float* __restrict__ out) {
    __shared__ int    soff[PB][36];
    __shared__ float2 scoef[PB][36];
    __shared__ float2 sc0[PB][JW];
    __shared__ float2 sc1[PB][JW];
    __shared__ int    si0[PB][JW];
    __shared__ int    si1[PB][JW];
    __shared__ float2 sph[PB];
    __shared__ float  sout[32 * PB];   // [c*2+comp][p]

    int b  = blockIdx.y;
    int m0 = blockIdx.x * PB;
    int t  = threadIdx.x;

    if (t < PB) {
        int m = m0 + t;
        float om0 = om[((size_t)b * 2 + 0) * MPTS + m];
        float om1 = om[((size_t)b * 2 + 1) * MPTS + m];
        const float S = (float)(KG / (2.0 * 3.14159265358979323846));
        float tm0 = om0 * S;
        float tm1 = om1 * S;
        int koff0 = (int)floorf(tm0 - 3.0f) + 1;
        int koff1 = (int)floorf(tm1 - 3.0f) + 1;
#pragma unroll
        for (int j = 0; j < JW; j++) {
            int g0   = koff0 + j;
            int idx0 = __float2int_rn((tm0 - (float)g0) * 1024.0f) + TCENTER;
            sc0[t][j] = make_float2(tab0[idx0], tab0[TLEN + idx0]);
            si0[t][j] = (g0 & (KG - 1)) * KG;
            int g1   = koff1 + j;
            int idx1 = __float2int_rn((tm1 - (float)g1) * 1024.0f) + TCENTER;
            sc1[t][j] = make_float2(tab1[idx1], tab1[TLEN + idx1]);
            si1[t][j] = g1 & (KG - 1);
        }
        float ph = om0 * nshift[0] + om1 * nshift[1];
        float sp, cp;
        sincosf(ph, &sp, &cp);
        sph[t] = make_float2(cp * GSCALE_I, sp * GSCALE_I);
    }
    __syncthreads();

    // fused 36 coefficients + element offsets per point
    for (int n = t; n < PB * 36; n += 256) {
        int p  = n / 36;
        int q  = n - p * 36;
        int a  = q / 6;
        int bb = q - a * 6;
        scoef[p][q] = cmulf(sc0[p][a], sc1[p][bb]);
        soff[p][q]  = (si0[p][a] + si1[p][bb]) * COILS;
    }
    __syncthreads();

    int p  = t >> 2;
    int q4 = (t & 3) * 4;   // coil base (4 coils per thread)
    const __half2* G = g_Gft + (size_t)b * KG * KG * COILS + q4;

    float2 a0 = make_float2(0.f, 0.f), a1 = a0, a2 = a0, a3 = a0;
#pragma unroll 6
    for (int n = 0; n < 36; n++) {
        int    off = soff[p][n];
        float2 cf  = scoef[p][n];
        float4 raw = *reinterpret_cast<const float4*>(G + off);
        __half2 h0 = *reinterpret_cast<__half2*>(&raw.x);
        __half2 h1 = *reinterpret_cast<__half2*>(&raw.y);
        __half2 h2 = *reinterpret_cast<__half2*>(&raw.z);
        __half2 h3 = *reinterpret_cast<__half2*>(&raw.w);
        float2 v0 = __half22float2(h0);
        float2 v1 = __half22float2(h1);
        float2 v2 = __half22float2(h2);
        float2 v3 = __half22float2(h3);
        a0.x += cf.x * v0.x - cf.y * v0.y;  a0.y += cf.x * v0.y + cf.y * v0.x;
        a1.x += cf.x * v1.x - cf.y * v1.y;  a1.y += cf.x * v1.y + cf.y * v1.x;
        a2.x += cf.x * v2.x - cf.y * v2.y;  a2.y += cf.x * v2.y + cf.y * v2.x;
        a3.x += cf.x * v3.x - cf.y * v3.y;  a3.y += cf.x * v3.y + cf.y * v3.x;
    }
    float2 ph = sph[p];
    float2 r0 = cmulf(a0, ph);
    float2 r1 = cmulf(a1, ph);
    float2 r2 = cmulf(a2, ph);
    float2 r3 = cmulf(a3, ph);

    sout[((q4 + 0) * 2 + 0) * PB + p] = r0.x;  sout[((q4 + 0) * 2 + 1) * PB + p] = r0.y;
    sout[((q4 + 1) * 2 + 0) * PB + p] = r1.x;  sout[((q4 + 1) * 2 + 1) * PB + p] = r1.y;
    sout[((q4 + 2) * 2 + 0) * PB + p] = r2.x;  sout[((q4 + 2) * 2 + 1) * PB + p] = r2.y;
    sout[((q4 + 3) * 2 + 0) * PB + p] = r3.x;  sout[((q4 + 3) * 2 + 1) * PB + p] = r3.y;
    __syncthreads();

    float* outp = out + (size_t)b * 2 * COILS * MPTS + m0;
#pragma unroll
    for (int i = 0; i < 8; i++) {
        int idx = i * 256 + t;
        int cr  = idx >> 6;       // c*2+comp
        int m   = idx & 63;
        outp[(size_t)cr * MPTS + m] = sout[idx];
    }
}

extern "C" void kernel_launch(void* const* d_in, const int* in_sizes, int n_in,
                              void* d_out, int out_size) {
    (void)in_sizes; (void)n_in; (void)out_size;
    const float* x      = (const float*)d_in[0];
    const float* om     = (const float*)d_in[1];
    const float* sc     = (const float*)d_in[2];
    const float* tab0   = (const float*)d_in[3];
    const float* tab1   = (const float*)d_in[4];
    const float* nshift = (const float*)d_in[5];
    float* out          = (float*)d_out;

    dim3 g1(NIM / 2, BATCH * COILS);
    pass1_rowfft<<<g1, 256>>>(x, sc);

    dim3 g2(KG / 4, BATCH * COILS);
    pass2_colfft<<<g2, 512>>>();

    dim3 g3(MPTS / PB, BATCH);
    interp_kernel<<<g3, 256>>>(om, tab0, tab1, nshift, out);
}

// round 6
// speedup vs baseline: 2.0217x; 1.2498x over previous
#include <cuda_runtime.h>
#include <cuda_fp16.h>
#include <math_constants.h>

#define BATCH  2
#define COILS  16
#define NIM    256
#define KG     512
#define JW     6
#define TCENTER 3072
#define TLEN   6145
#define MPTS   409600
#define GSCALE   0x1p-34f
#define GSCALE_I 0x1p34f

#define PADI(i) ((i) + ((i) >> 5))   // bank-conflict padding; max 511 -> 526
#define FFTBUF 528

// Scratch: row-FFT output (B,C,256,512) fp32 and transposed grid (B,512*512,C) fp16
static __device__ __align__(256) float2  g_Gr[(size_t)BATCH*COILS*NIM*KG];
static __device__ __align__(256) __half2 g_Gft[(size_t)BATCH*KG*KG*COILS];

__device__ __forceinline__ float2 cmulf(float2 a, float2 b) {
    return make_float2(a.x*b.x - a.y*b.y, a.x*b.y + a.y*b.x);
}

__device__ __forceinline__ float clampq(float v) {
    return fminf(fmaxf(v, -60000.0f), 60000.0f);
}

// 512-pt DIT FFT, 128 threads (tt in [0,128)), data pre-scattered to
// PADI(brev9(n)). 4 fused radix-4 stages + 1 radix-2 stage.
// tw[j] = exp(-i*pi*j/256). Caller must __syncthreads() before entry.
__device__ __forceinline__ void fft512_core(float* re, float* im,
                                            const float2* tw, int tt) {
#pragma unroll
    for (int h = 1; h <= 64; h *= 4) {
        int k    = tt & (h - 1);
        int base = 4 * tt - 3 * k;
        int i0 = PADI(base);
        int i1 = PADI(base + h);
        int i2 = PADI(base + 2 * h);
        int i3 = PADI(base + 3 * h);
        float ar = re[i0], ai = im[i0];
        float br = re[i1], bi = im[i1];
        float cr = re[i2], ci = im[i2];
        float dr = re[i3], di = im[i3];
        float2 w  = tw[k * (256 / h)];   // exp(-i*pi*k/h)
        float2 w1 = tw[k * (128 / h)];   // exp(-i*pi*k/(2h))
        // stage s (half = h)
        float t1r = w.x * br - w.y * bi, t1i = w.x * bi + w.y * br;
        float t2r = w.x * dr - w.y * di, t2i = w.x * di + w.y * dr;
        float Ar = ar + t1r, Ai = ai + t1i;
        float Br = ar - t1r, Bi = ai - t1i;
        float Cr = cr + t2r, Ci = ci + t2i;
        float Dr = cr - t2r, Di = ci - t2i;
        // stage s+1 (half = 2h); w2 = -i*w1
        float ur = w1.x * Cr - w1.y * Ci, ui = w1.x * Ci + w1.y * Cr;
        float vr = w1.y * Dr + w1.x * Di, vi = w1.y * Di - w1.x * Dr;
        re[i0] = Ar + ur;  im[i0] = Ai + ui;
        re[i2] = Ar - ur;  im[i2] = Ai - ui;
        re[i1] = Br + vr;  im[i1] = Bi + vi;
        re[i3] = Br - vr;  im[i3] = Bi - vi;
        __syncthreads();
    }
    // final radix-2 stage, half = 256
#pragma unroll
    for (int j = 0; j < 2; j++) {
        int i  = tt + 128 * j;
        int i0 = PADI(i);
        int i1 = PADI(i + 256);
        float2 w = tw[i];
        float ar = re[i0], ai = im[i0];
        float br = re[i1], bi = im[i1];
        float tr = w.x * br - w.y * bi, ti = w.x * bi + w.y * br;
        re[i0] = ar + tr;  im[i0] = ai + ti;
        re[i1] = ar - tr;  im[i1] = ai - ti;
    }
    __syncthreads();
}

// ---------------------------------------------------------------------------
// Pass 1: apodize + row FFT. 2 rows per 256-thread block. grid(128, B*C).
// ---------------------------------------------------------------------------
__global__ __launch_bounds__(256) void pass1_rowfft(const float* __restrict__ x,
                                                    const float* __restrict__ sc) {
    __shared__ float  s_re[2][FFTBUF];
    __shared__ float  s_im[2][FFTBUF];
    __shared__ float2 tw[256];
    int tid = threadIdx.x;
    int f   = tid >> 7;
    int tt  = tid & 127;
    int r   = blockIdx.x * 2 + f;
    int bc  = blockIdx.y;

    {
        float ang = -CUDART_PI_F * (float)tid / 256.0f;
        float s, c; sincosf(ang, &s, &c);
        tw[tid] = make_float2(c, s);
    }

    float* re = s_re[f];
    float* im = s_im[f];

    const float* xr  = x  + ((size_t)bc * 2 + 0) * (NIM * NIM) + (size_t)r * NIM;
    const float* xi  = x  + ((size_t)bc * 2 + 1) * (NIM * NIM) + (size_t)r * NIM;
    const float* scr = sc + (size_t)r * NIM;
    const float* sci = sc + (size_t)NIM * NIM + (size_t)r * NIM;

#pragma unroll
    for (int j = 0; j < 2; j++) {
        int n = tt + 128 * j;
        float a = xr[n], b = xi[n], cr = scr[n], ci = sci[n];
        int d = PADI(__brev(n) >> 23);
        re[d] = a * cr - b * ci;
        im[d] = a * ci + b * cr;
    }
#pragma unroll
    for (int j = 2; j < 4; j++) {
        int n = tt + 128 * j;
        int d = PADI(__brev(n) >> 23);
        re[d] = 0.f;
        im[d] = 0.f;
    }
    __syncthreads();

    fft512_core(re, im, tw, tt);

    float2* out = g_Gr + ((size_t)bc * NIM + r) * KG;
#pragma unroll
    for (int j = 0; j < 4; j++) {
        int n = tt + 128 * j;
        int d = PADI(n);
        out[n] = make_float2(re[d], im[d]);
    }
}

// ---------------------------------------------------------------------------
// Pass 2: column FFT for ALL 16 coils of one column per block, staged in smem,
// then one fully-coalesced fp16 write phase. grid(KG, BATCH), 256 threads.
// 2 concurrent FFTs (f = tid>>7) x 8 rounds over coil pairs.
// ---------------------------------------------------------------------------
__global__ __launch_bounds__(256) void pass2_colfft() {
    __shared__ float   s_re[2][FFTBUF];
    __shared__ float   s_im[2][FFTBUF];
    __shared__ float2  tw[256];
    __shared__ __half2 stage[512 * 17];   // stage[n*17 + c], padded vs bank conflicts

    int tid = threadIdx.x;
    int f   = tid >> 7;
    int tt  = tid & 127;
    int col = blockIdx.x;
    int b   = blockIdx.y;

    {
        float ang = -CUDART_PI_F * (float)tid / 256.0f;
        float s, cc; sincosf(ang, &s, &cc);
        tw[tid] = make_float2(cc, s);
    }

    float* re = s_re[f];
    float* im = s_im[f];

#pragma unroll 1
    for (int cc = 0; cc < 8; cc++) {
        int c = cc * 2 + f;
        const float2* in = g_Gr + ((size_t)(b * COILS + c) * NIM) * KG + col;
#pragma unroll
        for (int j = 0; j < 2; j++) {
            int n = tt + 128 * j;
            float2 v = in[(size_t)n * KG];
            int d = PADI(__brev(n) >> 23);
            re[d] = v.x;
            im[d] = v.y;
        }
#pragma unroll
        for (int j = 2; j < 4; j++) {
            int n = tt + 128 * j;
            int d = PADI(__brev(n) >> 23);
            re[d] = 0.f;
            im[d] = 0.f;
        }
        __syncthreads();

        fft512_core(re, im, tw, tt);   // ends with __syncthreads()

#pragma unroll
        for (int j = 0; j < 4; j++) {
            int n = tt + 128 * j;
            int d = PADI(n);
            stage[n * 17 + c] =
                __floats2half2_rn(clampq(re[d] * GSCALE), clampq(im[d] * GSCALE));
        }
        __syncthreads();   // stage reads of re/im done before next round overwrites
    }

    // Coalesced write: consecutive threads -> consecutive coils (64B segments).
    __half2* out = g_Gft + (size_t)b * KG * KG * COILS + (size_t)col * COILS;
#pragma unroll
    for (int i = 0; i < 32; i++) {
        int idx = i * 256 + tid;      // idx = n*16 + c
        int n   = idx >> 4;
        int c   = idx & 15;
        out[(size_t)n * (KG * COILS) + c] = stage[n * 17 + c];
    }
}

// ---------------------------------------------------------------------------
// Interpolation: 64 points x 4 threads (4 coils each) per block. grid(M/64, B).
// On-the-fly coefficient fusion; 17.9KB smem -> 2048 thr/SM occupancy.
// ---------------------------------------------------------------------------
#define PB 64
__global__ __launch_bounds__(256) void interp_kernel(const float* __restrict__ om,
                                                     const float* __restrict__ tab0,
                                                     const float* __restrict__ tab1,
                                                     const float* __restrict__ nshift,
                                                     float* __restrict__ out) {
    __shared__ float2 sc0[PB][JW];
    __shared__ float2 sc1[PB][JW];
    __shared__ int    si0[PB][JW];   // row * KG
    __shared__ int    si1[PB][JW];
    __shared__ float2 sph[PB];
    __shared__ float  sout[32 * PB];   // [c*2+comp][p]

    int b  = blockIdx.y;
    int m0 = blockIdx.x * PB;
    int t  = threadIdx.x;

    if (t < PB) {
        int m = m0 + t;
        float om0 = om[((size_t)b * 2 + 0) * MPTS + m];
        float om1 = om[((size_t)b * 2 + 1) * MPTS + m];
        const float S = (float)(KG / (2.0 * 3.14159265358979323846));
        float tm0 = om0 * S;
        float tm1 = om1 * S;
        int koff0 = (int)floorf(tm0 - 3.0f) + 1;
        int koff1 = (int)floorf(tm1 - 3.0f) + 1;
#pragma unroll
        for (int j = 0; j < JW; j++) {
            int g0   = koff0 + j;
            int idx0 = __float2int_rn((tm0 - (float)g0) * 1024.0f) + TCENTER;
            sc0[t][j] = make_float2(tab0[idx0], tab0[TLEN + idx0]);
            si0[t][j] = (g0 & (KG - 1)) * KG;
            int g1   = koff1 + j;
            int idx1 = __float2int_rn((tm1 - (float)g1) * 1024.0f) + TCENTER;
            sc1[t][j] = make_float2(tab1[idx1], tab1[TLEN + idx1]);
            si1[t][j] = g1 & (KG - 1);
        }
        float ph = om0 * nshift[0] + om1 * nshift[1];
        float sp, cp;
        sincosf(ph, &sp, &cp);
        sph[t] = make_float2(cp * GSCALE_I, sp * GSCALE_I);
    }
    __syncthreads();

    int p  = t >> 2;
    int q4 = (t & 3) * 4;   // coil base (4 coils per thread)
    const __half2* G = g_Gft + (size_t)b * KG * KG * COILS + q4;

    float2 a0 = make_float2(0.f, 0.f), a1 = a0, a2 = a0, a3 = a0;
#pragma unroll
    for (int a = 0; a < JW; a++) {
        float2 ca   = sc0[p][a];
        int    roff = si0[p][a];
#pragma unroll
        for (int bb = 0; bb < JW; bb++) {
            float2 cf  = cmulf(ca, sc1[p][bb]);
            int    off = (roff + si1[p][bb]) * COILS;
            float4 raw = *reinterpret_cast<const float4*>(G + off);
            __half2 h0 = *reinterpret_cast<__half2*>(&raw.x);
            __half2 h1 = *reinterpret_cast<__half2*>(&raw.y);
            __half2 h2 = *reinterpret_cast<__half2*>(&raw.z);
            __half2 h3 = *reinterpret_cast<__half2*>(&raw.w);
            float2 v0 = __half22float2(h0);
            float2 v1 = __half22float2(h1);
            float2 v2 = __half22float2(h2);
            float2 v3 = __half22float2(h3);
            a0.x += cf.x * v0.x - cf.y * v0.y;  a0.y += cf.x * v0.y + cf.y * v0.x;
            a1.x += cf.x * v1.x - cf.y * v1.y;  a1.y += cf.x * v1.y + cf.y * v1.x;
            a2.x += cf.x * v2.x - cf.y * v2.y;  a2.y += cf.x * v2.y + cf.y * v2.x;
            a3.x += cf.x * v3.x - cf.y * v3.y;  a3.y += cf.x * v3.y + cf.y * v3.x;
        }
    }
    float2 ph = sph[p];
    float2 r0 = cmulf(a0, ph);
    float2 r1 = cmulf(a1, ph);
    float2 r2 = cmulf(a2, ph);
    float2 r3 = cmulf(a3, ph);

    sout[((q4 + 0) * 2 + 0) * PB + p] = r0.x;  sout[((q4 + 0) * 2 + 1) * PB + p] = r0.y;
    sout[((q4 + 1) * 2 + 0) * PB + p] = r1.x;  sout[((q4 + 1) * 2 + 1) * PB + p] = r1.y;
    sout[((q4 + 2) * 2 + 0) * PB + p] = r2.x;  sout[((q4 + 2) * 2 + 1) * PB + p] = r2.y;
    sout[((q4 + 3) * 2 + 0) * PB + p] = r3.x;  sout[((q4 + 3) * 2 + 1) * PB + p] = r3.y;
    __syncthreads();

    float* outp = out + (size_t)b * 2 * COILS * MPTS + m0;
#pragma unroll
    for (int i = 0; i < 8; i++) {
        int idx = i * 256 + t;
        int cr  = idx >> 6;       // c*2+comp
        int m   = idx & 63;
        outp[(size_t)cr * MPTS + m] = sout[idx];
    }
}

extern "C" void kernel_launch(void* const* d_in, const int* in_sizes, int n_in,
                              void* d_out, int out_size) {
    (void)in_sizes; (void)n_in; (void)out_size;
    const float* x      = (const float*)d_in[0];
    const float* om     = (const float*)d_in[1];
    const float* sc     = (const float*)d_in[2];
    const float* tab0   = (const float*)d_in[3];
    const float* tab1   = (const float*)d_in[4];
    const float* nshift = (const float*)d_in[5];
    float* out          = (float*)d_out;

    dim3 g1(NIM / 2, BATCH * COILS);
    pass1_rowfft<<<g1, 256>>>(x, sc);

    dim3 g2(KG, BATCH);
    pass2_colfft<<<g2, 256>>>();

    dim3 g3(MPTS / PB, BATCH);
    interp_kernel<<<g3, 256>>>(om, tab0, tab1, nshift, out);
}

// round 9
// speedup vs baseline: 2.1569x; 1.0669x over previous
#include <cuda_runtime.h>
#include <cuda_fp16.h>
#include <math_constants.h>

#define BATCH  2
#define COILS  16
#define NIM    256
#define KG     512
#define JW     6
#define TCENTER 3072
#define TLEN   6145
#define MPTS   409600
#define GSCALE   0x1p-34f
#define GSCALE_I 0x1p34f

#define PADI(i) ((i) + ((i) >> 5))   // bank-conflict padding; max 511 -> 526
#define FFTBUF 528

// Scratch: row-FFT output (B,C,256,512) fp32 and transposed grid (B,512*512,C) fp16
static __device__ __align__(256) float2  g_Gr[(size_t)BATCH*COILS*NIM*KG];
static __device__ __align__(256) __half2 g_Gft[(size_t)BATCH*KG*KG*COILS];

__device__ __forceinline__ float2 cmulf(float2 a, float2 b) {
    return make_float2(a.x*b.x - a.y*b.y, a.x*b.y + a.y*b.x);
}

__device__ __forceinline__ float clampq(float v) {
    return fminf(fmaxf(v, -60000.0f), 60000.0f);
}

// ---- packed f32x2 helpers (sm_103a) ----
__device__ __forceinline__ unsigned long long pk2(float lo, float hi) {
    unsigned long long r;
    asm("mov.b64 %0, {%1, %2};" : "=l"(r) : "f"(lo), "f"(hi));
    return r;
}
__device__ __forceinline__ void upk2(float& lo, float& hi, unsigned long long v) {
    asm("mov.b64 {%0, %1}, %2;" : "=f"(lo), "=f"(hi) : "l"(v));
}
__device__ __forceinline__ void fma2(unsigned long long& d,
                                     unsigned long long a,
                                     unsigned long long b) {
    asm("fma.rn.f32x2 %0, %1, %2, %0;" : "+l"(d) : "l"(a), "l"(b));
}

// 512-pt DIT FFT, 128 threads (tt in [0,128)), data pre-scattered to
// PADI(brev9(n)). 4 fused radix-4 stages + 1 radix-2 stage.
// tw[j] = exp(-i*pi*j/256). Caller must __syncthreads() before entry.
__device__ __forceinline__ void fft512_core(float* re, float* im,
                                            const float2* tw, int tt) {
#pragma unroll
    for (int h = 1; h <= 64; h *= 4) {
        int k    = tt & (h - 1);
        int base = 4 * tt - 3 * k;
        int i0 = PADI(base);
        int i1 = PADI(base + h);
        int i2 = PADI(base + 2 * h);
        int i3 = PADI(base + 3 * h);
        float ar = re[i0], ai = im[i0];
        float br = re[i1], bi = im[i1];
        float cr = re[i2], ci = im[i2];
        float dr = re[i3], di = im[i3];
        float2 w  = tw[k * (256 / h)];   // exp(-i*pi*k/h)
        float2 w1 = tw[k * (128 / h)];   // exp(-i*pi*k/(2h))
        // stage s (half = h)
        float t1r = w.x * br - w.y * bi, t1i = w.x * bi + w.y * br;
        float t2r = w.x * dr - w.y * di, t2i = w.x * di + w.y * dr;
        float Ar = ar + t1r, Ai = ai + t1i;
        float Br = ar - t1r, Bi = ai - t1i;
        float Cr = cr + t2r, Ci = ci + t2i;
        float Dr = cr - t2r, Di = ci - t2i;
        // stage s+1 (half = 2h); w2 = -i*w1
        float ur = w1.x * Cr - w1.y * Ci, ui = w1.x * Ci + w1.y * Cr;
        float vr = w1.y * Dr + w1.x * Di, vi = w1.y * Di - w1.x * Dr;
        re[i0] = Ar + ur;  im[i0] = Ai + ui;
        re[i2] = Ar - ur;  im[i2] = Ai - ui;
        re[i1] = Br + vr;  im[i1] = Bi + vi;
        re[i3] = Br - vr;  im[i3] = Bi - vi;
        __syncthreads();
    }
    // final radix-2 stage, half = 256
#pragma unroll
    for (int j = 0; j < 2; j++) {
        int i  = tt + 128 * j;
        int i0 = PADI(i);
        int i1 = PADI(i + 256);
        float2 w = tw[i];
        float ar = re[i0], ai = im[i0];
        float br = re[i1], bi = im[i1];
        float tr = w.x * br - w.y * bi, ti = w.x * bi + w.y * br;
        re[i0] = ar + tr;  im[i0] = ai + ti;
        re[i1] = ar - tr;  im[i1] = ai - ti;
    }
    __syncthreads();
}

// ---------------------------------------------------------------------------
// Pass 1: apodize + row FFT. 2 rows per 256-thread block. grid(128, B*C).
// ---------------------------------------------------------------------------
__global__ __launch_bounds__(256) void pass1_rowfft(const float* __restrict__ x,
                                                    const float* __restrict__ sc) {
    __shared__ float  s_re[2][FFTBUF];
    __shared__ float  s_im[2][FFTBUF];
    __shared__ float2 tw[256];
    int tid = threadIdx.x;
    int f   = tid >> 7;
    int tt  = tid & 127;
    int r   = blockIdx.x * 2 + f;
    int bc  = blockIdx.y;

    {
        float ang = -CUDART_PI_F * (float)tid / 256.0f;
        float s, c; sincosf(ang, &s, &c);
        tw[tid] = make_float2(c, s);
    }

    float* re = s_re[f];
    float* im = s_im[f];

    const float* xr  = x  + ((size_t)bc * 2 + 0) * (NIM * NIM) + (size_t)r * NIM;
    const float* xi  = x  + ((size_t)bc * 2 + 1) * (NIM * NIM) + (size_t)r * NIM;
    const float* scr = sc + (size_t)r * NIM;
    const float* sci = sc + (size_t)NIM * NIM + (size_t)r * NIM;

#pragma unroll
    for (int j = 0; j < 2; j++) {
        int n = tt + 128 * j;
        float a = xr[n], b = xi[n], cr = scr[n], ci = sci[n];
        int d = PADI(__brev(n) >> 23);
        re[d] = a * cr - b * ci;
        im[d] = a * ci + b * cr;
    }
#pragma unroll
    for (int j = 2; j < 4; j++) {
        int n = tt + 128 * j;
        int d = PADI(__brev(n) >> 23);
        re[d] = 0.f;
        im[d] = 0.f;
    }
    __syncthreads();

    fft512_core(re, im, tw, tt);

    float2* out = g_Gr + ((size_t)bc * NIM + r) * KG;
#pragma unroll
    for (int j = 0; j < 4; j++) {
        int n = tt + 128 * j;
        int d = PADI(n);
        out[n] = make_float2(re[d], im[d]);
    }
}

// ---------------------------------------------------------------------------
// Pass 2: column FFT for ALL 16 coils of one column per block, staged in smem,
// then one fully-coalesced fp16 write phase. grid(KG, BATCH), 256 threads.
// 2 concurrent FFTs (f = tid>>7) x 8 rounds over coil pairs.
// ---------------------------------------------------------------------------
__global__ __launch_bounds__(256) void pass2_colfft() {
    __shared__ float   s_re[2][FFTBUF];
    __shared__ float   s_im[2][FFTBUF];
    __shared__ float2  tw[256];
    __shared__ __half2 stage[512 * 17];   // stage[n*17 + c], padded vs bank conflicts

    int tid = threadIdx.x;
    int f   = tid >> 7;
    int tt  = tid & 127;
    int col = blockIdx.x;
    int b   = blockIdx.y;

    {
        float ang = -CUDART_PI_F * (float)tid / 256.0f;
        float s, cc; sincosf(ang, &s, &cc);
        tw[tid] = make_float2(cc, s);
    }

    float* re = s_re[f];
    float* im = s_im[f];

#pragma unroll 1
    for (int cc = 0; cc < 8; cc++) {
        int c = cc * 2 + f;
        const float2* in = g_Gr + ((size_t)(b * COILS + c) * NIM) * KG + col;
#pragma unroll
        for (int j = 0; j < 2; j++) {
            int n = tt + 128 * j;
            float2 v = in[(size_t)n * KG];
            int d = PADI(__brev(n) >> 23);
            re[d] = v.x;
            im[d] = v.y;
        }
#pragma unroll
        for (int j = 2; j < 4; j++) {
            int n = tt + 128 * j;
            int d = PADI(__brev(n) >> 23);
            re[d] = 0.f;
            im[d] = 0.f;
        }
        __syncthreads();

        fft512_core(re, im, tw, tt);   // ends with __syncthreads()

#pragma unroll
        for (int j = 0; j < 4; j++) {
            int n = tt + 128 * j;
            int d = PADI(n);
            stage[n * 17 + c] =
                __floats2half2_rn(clampq(re[d] * GSCALE), clampq(im[d] * GSCALE));
        }
        __syncthreads();   // stage reads of re/im done before next round overwrites
    }

    // Coalesced write: consecutive threads -> consecutive coils (64B segments).
    __half2* out = g_Gft + (size_t)b * KG * KG * COILS + (size_t)col * COILS;
#pragma unroll
    for (int i = 0; i < 32; i++) {
        int idx = i * 256 + tid;      // idx = n*16 + c
        int n   = idx >> 4;
        int c   = idx & 15;
        out[(size_t)n * (KG * COILS) + c] = stage[n * 17 + c];
    }
}

// ---------------------------------------------------------------------------
// Interpolation: 64 points x 4 threads (4 coils each) per block. grid(M/64, B).
// Packed f32x2 FMA accumulation + 3-deep load batching.
// ---------------------------------------------------------------------------
#define PB 64
__global__ __launch_bounds__(256) void interp_kernel(const float* __restrict__ om,
                                                     const float* __restrict__ tab0,
                                                     const float* __restrict__ tab1,
                                                     const float* __restrict__ nshift,
                                                     float* __restrict__ out) {
    __shared__ float2 sc0[PB][JW];
    __shared__ float2 sc1[PB][JW];
    __shared__ int    si0[PB][JW];   // row * KG * COILS
    __shared__ int    si1[PB][JW];   // col * COILS
    __shared__ float2 sph[PB];
    __shared__ float  sout[32 * PB];   // [c*2+comp][p]

    int b  = blockIdx.y;
    int m0 = blockIdx.x * PB;
    int t  = threadIdx.x;

    if (t < PB) {
        int m = m0 + t;
        float om0 = om[((size_t)b * 2 + 0) * MPTS + m];
        float om1 = om[((size_t)b * 2 + 1) * MPTS + m];
        const float S = (float)(KG / (2.0 * 3.14159265358979323846));
        float tm0 = om0 * S;
        float tm1 = om1 * S;
        int koff0 = (int)floorf(tm0 - 3.0f) + 1;
        int koff1 = (int)floorf(tm1 - 3.0f) + 1;
#pragma unroll
        for (int j = 0; j < JW; j++) {
            int g0   = koff0 + j;
            int idx0 = __float2int_rn((tm0 - (float)g0) * 1024.0f) + TCENTER;
            sc0[t][j] = make_float2(tab0[idx0], tab0[TLEN + idx0]);
            si0[t][j] = (g0 & (KG - 1)) * (KG * COILS);
            int g1   = koff1 + j;
            int idx1 = __float2int_rn((tm1 - (float)g1) * 1024.0f) + TCENTER;
            sc1[t][j] = make_float2(tab1[idx1], tab1[TLEN + idx1]);
            si1[t][j] = (g1 & (KG - 1)) * COILS;
        }
        float ph = om0 * nshift[0] + om1 * nshift[1];
        float sp, cp;
        sincosf(ph, &sp, &cp);
        sph[t] = make_float2(cp * GSCALE_I, sp * GSCALE_I);
    }
    __syncthreads();

    int p  = t >> 2;
    int q4 = (t & 3) * 4;   // coil base (4 coils per thread)
    const __half2* G = g_Gft + (size_t)b * KG * KG * COILS + q4;

    unsigned long long acc0 = pk2(0.f, 0.f);
    unsigned long long acc1 = acc0, acc2 = acc0, acc3 = acc0;

#pragma unroll
    for (int a = 0; a < JW; a++) {
        float2 ca   = sc0[p][a];
        int    roff = si0[p][a];
#pragma unroll
        for (int g = 0; g < 2; g++) {
            float4 raw0 = *reinterpret_cast<const float4*>(G + roff + si1[p][g * 3 + 0]);
            float4 raw1 = *reinterpret_cast<const float4*>(G + roff + si1[p][g * 3 + 1]);
            float4 raw2 = *reinterpret_cast<const float4*>(G + roff + si1[p][g * 3 + 2]);
#pragma unroll
            for (int u = 0; u < 3; u++) {
                float4 raw = (u == 0) ? raw0 : (u == 1) ? raw1 : raw2;
                float2 cf  = cmulf(ca, sc1[p][g * 3 + u]);
                unsigned long long cxx = pk2(cf.x, cf.x);
                unsigned long long cyn = pk2(-cf.y, cf.y);
                float2 v0 = __half22float2(*reinterpret_cast<__half2*>(&raw.x));
                float2 v1 = __half22float2(*reinterpret_cast<__half2*>(&raw.y));
                float2 v2 = __half22float2(*reinterpret_cast<__half2*>(&raw.z));
                float2 v3 = __half22float2(*reinterpret_cast<__half2*>(&raw.w));
                fma2(acc0, pk2(v0.x, v0.y), cxx);
                fma2(acc0, pk2(v0.y, v0.x), cyn);
                fma2(acc1, pk2(v1.x, v1.y), cxx);
                fma2(acc1, pk2(v1.y, v1.x), cyn);
                fma2(acc2, pk2(v2.x, v2.y), cxx);
                fma2(acc2, pk2(v2.y, v2.x), cyn);
                fma2(acc3, pk2(v3.x, v3.y), cxx);
                fma2(acc3, pk2(v3.y, v3.x), cyn);
            }
        }
    }

    float2 a0, a1, a2, a3;
    upk2(a0.x, a0.y, acc0);
    upk2(a1.x, a1.y, acc1);
    upk2(a2.x, a2.y, acc2);
    upk2(a3.x, a3.y, acc3);

    float2 ph = sph[p];
    float2 r0 = cmulf(a0, ph);
    float2 r1 = cmulf(a1, ph);
    float2 r2 = cmulf(a2, ph);
    float2 r3 = cmulf(a3, ph);

    sout[((q4 + 0) * 2 + 0) * PB + p] = r0.x;  sout[((q4 + 0) * 2 + 1) * PB + p] = r0.y;
    sout[((q4 + 1) * 2 + 0) * PB + p] = r1.x;  sout[((q4 + 1) * 2 + 1) * PB + p] = r1.y;
    sout[((q4 + 2) * 2 + 0) * PB + p] = r2.x;  sout[((q4 + 2) * 2 + 1) * PB + p] = r2.y;
    sout[((q4 + 3) * 2 + 0) * PB + p] = r3.x;  sout[((q4 + 3) * 2 + 1) * PB + p] = r3.y;
    __syncthreads();

    float* outp = out + (size_t)b * 2 * COILS * MPTS + m0;
#pragma unroll
    for (int i = 0; i < 8; i++) {
        int idx = i * 256 + t;
        int cr  = idx >> 6;       // c*2+comp
        int m   = idx & 63;
        outp[(size_t)cr * MPTS + m] = sout[idx];
    }
}

extern "C" void kernel_launch(void* const* d_in, const int* in_sizes, int n_in,
                              void* d_out, int out_size) {
    (void)in_sizes; (void)n_in; (void)out_size;
    const float* x      = (const float*)d_in[0];
    const float* om     = (const float*)d_in[1];
    const float* sc     = (const float*)d_in[2];
    const float* tab0   = (const float*)d_in[3];
    const float* tab1   = (const float*)d_in[4];
    const float* nshift = (const float*)d_in[5];
    float* out          = (float*)d_out;

    dim3 g1(NIM / 2, BATCH * COILS);
    pass1_rowfft<<<g1, 256>>>(x, sc);

    dim3 g2(KG, BATCH);
    pass2_colfft<<<g2, 256>>>();

    dim3 g3(MPTS / PB, BATCH);
    interp_kernel<<<g3, 256>>>(om, tab0, tab1, nshift, out);
}

// round 10
// speedup vs baseline: 2.4510x; 1.1364x over previous
#include <cuda_runtime.h>
#include <cuda_fp16.h>
#include <math_constants.h>

#define BATCH  2
#define COILS  16
#define NIM    256
#define KG     512
#define JW     6
#define TCENTER 3072
#define TLEN   6145
#define MPTS   409600
#define GSCALE   0x1p-34f
#define GSCALE_I 0x1p34f

#define PADI(i) ((i) + ((i) >> 5))   // bank-conflict padding; max 511 -> 526
#define FFTBUF 528

// Scratch: row-FFT output (B,C,256,512) fp32 and transposed grid (B,512*512,C) fp16
static __device__ __align__(256) float2  g_Gr[(size_t)BATCH*COILS*NIM*KG];
static __device__ __align__(256) __half2 g_Gft[(size_t)BATCH*KG*KG*COILS];

__device__ __forceinline__ float2 cmulf(float2 a, float2 b) {
    return make_float2(a.x*b.x - a.y*b.y, a.x*b.y + a.y*b.x);
}

__device__ __forceinline__ float clampq(float v) {
    return fminf(fmaxf(v, -60000.0f), 60000.0f);
}

// ---- packed f32x2 helpers (sm_103a) ----
__device__ __forceinline__ unsigned long long pk2(float lo, float hi) {
    unsigned long long r;
    asm("mov.b64 %0, {%1, %2};" : "=l"(r) : "f"(lo), "f"(hi));
    return r;
}
__device__ __forceinline__ void upk2(float& lo, float& hi, unsigned long long v) {
    asm("mov.b64 {%0, %1}, %2;" : "=f"(lo), "=f"(hi) : "l"(v));
}
__device__ __forceinline__ void fma2(unsigned long long& d,
                                     unsigned long long a,
                                     unsigned long long b) {
    asm("fma.rn.f32x2 %0, %1, %2, %0;" : "+l"(d) : "l"(a), "l"(b));
}

// ---------------------------------------------------------------------------
// Straight-line 8-point DFT, natural-order in/out. X[k] = sum_i x[i] w8^{ik}.
// ---------------------------------------------------------------------------
__device__ __forceinline__ void dft8(float2 x[8]) {
    const float RH = 0.70710678118654752f;
    // FFT4 of even samples (x0,x2,x4,x6)
    float2 ec0 = make_float2(x[0].x + x[4].x, x[0].y + x[4].y);
    float2 ec1 = make_float2(x[0].x - x[4].x, x[0].y - x[4].y);
    float2 ec2 = make_float2(x[2].x + x[6].x, x[2].y + x[6].y);
    float2 ec3 = make_float2(x[2].x - x[6].x, x[2].y - x[6].y);
    float2 E0 = make_float2(ec0.x + ec2.x, ec0.y + ec2.y);
    float2 E2 = make_float2(ec0.x - ec2.x, ec0.y - ec2.y);
    float2 E1 = make_float2(ec1.x + ec3.y, ec1.y - ec3.x);   // c1 - i c3
    float2 E3 = make_float2(ec1.x - ec3.y, ec1.y + ec3.x);   // c1 + i c3
    // FFT4 of odd samples (x1,x3,x5,x7)
    float2 oc0 = make_float2(x[1].x + x[5].x, x[1].y + x[5].y);
    float2 oc1 = make_float2(x[1].x - x[5].x, x[1].y - x[5].y);
    float2 oc2 = make_float2(x[3].x + x[7].x, x[3].y + x[7].y);
    float2 oc3 = make_float2(x[3].x - x[7].x, x[3].y - x[7].y);
    float2 O0 = make_float2(oc0.x + oc2.x, oc0.y + oc2.y);
    float2 O2 = make_float2(oc0.x - oc2.x, oc0.y - oc2.y);
    float2 O1 = make_float2(oc1.x + oc3.y, oc1.y - oc3.x);
    float2 O3 = make_float2(oc1.x - oc3.y, oc1.y + oc3.x);
    // combine with w8^k
    float2 t1 = make_float2(RH * (O1.x + O1.y), RH * (O1.y - O1.x));    // w8^1 * O1
    float2 t2 = make_float2(O2.y, -O2.x);                               // -i * O2
    float2 t3 = make_float2(RH * (O3.y - O3.x), -RH * (O3.x + O3.y));   // w8^3 * O3
    x[0] = make_float2(E0.x + O0.x, E0.y + O0.y);
    x[4] = make_float2(E0.x - O0.x, E0.y - O0.y);
    x[1] = make_float2(E1.x + t1.x, E1.y + t1.y);
    x[5] = make_float2(E1.x - t1.x, E1.y - t1.y);
    x[2] = make_float2(E2.x + t2.x, E2.y + t2.y);
    x[6] = make_float2(E2.x - t2.x, E2.y - t2.y);
    x[3] = make_float2(E3.x + t3.x, E3.y + t3.y);
    x[7] = make_float2(E3.x - t3.x, E3.y - t3.y);
}

// 512-pt FFT as 3 radix-8 stages, 64 threads (tt in [0,64)).
// Input must be scattered to PADI(digitrev8(n)); output natural at PADI(n).
// tw512[j] = exp(-2*pi*i*j/512). Caller syncs before entry.
__device__ __forceinline__ void fft512_r8(float* re, float* im,
                                          const float2* tw512, int tt) {
    float2 x[8];
    // stage 1: h=1, base = 8*tt, no twiddles
    {
        int base = 8 * tt;
#pragma unroll
        for (int i = 0; i < 8; i++) {
            int a = PADI(base + i);
            x[i] = make_float2(re[a], im[a]);
        }
        dft8(x);
#pragma unroll
        for (int i = 0; i < 8; i++) {
            int a = PADI(base + i);
            re[a] = x[i].x; im[a] = x[i].y;
        }
    }
    __syncthreads();
    // stage 2: h=8; g = tt&7, r = tt>>3; addr = 64g + r + 8i; tw = tw512[8*r*i]
    {
        int g = tt & 7, r = tt >> 3;
        int base = 64 * g + r;
#pragma unroll
        for (int i = 0; i < 8; i++) {
            int a = PADI(base + 8 * i);
            x[i] = make_float2(re[a], im[a]);
        }
#pragma unroll
        for (int i = 1; i < 8; i++)
            x[i] = cmulf(x[i], tw512[(8 * r * i) & 511]);
        dft8(x);
#pragma unroll
        for (int i = 0; i < 8; i++) {
            int a = PADI(base + 8 * i);
            re[a] = x[i].x; im[a] = x[i].y;
        }
    }
    __syncthreads();
    // stage 3: h=64; r = tt; addr = r + 64i; tw = tw512[r*i]
    {
#pragma unroll
        for (int i = 0; i < 8; i++) {
            int a = PADI(tt + 64 * i);
            x[i] = make_float2(re[a], im[a]);
        }
#pragma unroll
        for (int i = 1; i < 8; i++)
            x[i] = cmulf(x[i], tw512[(tt * i) & 511]);
        dft8(x);
#pragma unroll
        for (int i = 0; i < 8; i++) {
            int a = PADI(tt + 64 * i);
            re[a] = x[i].x; im[a] = x[i].y;
        }
    }
    __syncthreads();
}

__device__ __forceinline__ int digitrev8(int n) {
    return ((n & 7) << 6) | (((n >> 3) & 7) << 3) | (n >> 6);
}

// ---------------------------------------------------------------------------
// Pass 1: apodize + row FFT. 4 rows per 256-thread block. grid(64, B*C).
// ---------------------------------------------------------------------------
__global__ __launch_bounds__(256) void pass1_rowfft(const float* __restrict__ x,
                                                    const float* __restrict__ sc) {
    __shared__ float  s_re[4][FFTBUF];
    __shared__ float  s_im[4][FFTBUF];
    __shared__ float2 tw512[512];
    int tid = threadIdx.x;
    int f   = tid >> 6;
    int tt  = tid & 63;
    int r   = blockIdx.x * 4 + f;
    int bc  = blockIdx.y;

#pragma unroll
    for (int j = 0; j < 2; j++) {
        int idx = tid + 256 * j;
        float ang = -CUDART_PI_F * (float)idx / 256.0f;   // -2*pi*idx/512
        float s, c; sincosf(ang, &s, &c);
        tw512[idx] = make_float2(c, s);
    }

    float* re = s_re[f];
    float* im = s_im[f];

    const float* xr  = x  + ((size_t)bc * 2 + 0) * (NIM * NIM) + (size_t)r * NIM;
    const float* xi  = x  + ((size_t)bc * 2 + 1) * (NIM * NIM) + (size_t)r * NIM;
    const float* scr = sc + (size_t)r * NIM;
    const float* sci = sc + (size_t)NIM * NIM + (size_t)r * NIM;

#pragma unroll
    for (int j = 0; j < 4; j++) {
        int n = tt + 64 * j;
        float a = xr[n], b = xi[n], cr = scr[n], ci = sci[n];
        int d = PADI(digitrev8(n));
        re[d] = a * cr - b * ci;
        im[d] = a * ci + b * cr;
    }
#pragma unroll
    for (int j = 4; j < 8; j++) {
        int d = PADI(digitrev8(tt + 64 * j));
        re[d] = 0.f;
        im[d] = 0.f;
    }
    __syncthreads();

    fft512_r8(re, im, tw512, tt);

    float2* out = g_Gr + ((size_t)bc * NIM + r) * KG;
#pragma unroll
    for (int j = 0; j < 8; j++) {
        int n = tt + 64 * j;
        int d = PADI(n);
        out[n] = make_float2(re[d], im[d]);
    }
}

// ---------------------------------------------------------------------------
// Pass 2: column FFT for ALL 16 coils of one column per block, staged in smem,
// then one fully-coalesced fp16 write phase. grid(KG, BATCH), 256 threads.
// 4 concurrent radix-8 FFTs (f = tid>>6) x 4 rounds over coils. Dynamic smem.
// ---------------------------------------------------------------------------
#define P2_SMEM (4 * FFTBUF * 2 * 4 + 512 * 8 + 512 * 17 * 4)
__global__ __launch_bounds__(256) void pass2_colfft() {
    extern __shared__ char smem2[];
    float*   s_re  = (float*)smem2;                        // [4][FFTBUF]
    float*   s_im  = s_re + 4 * FFTBUF;                    // [4][FFTBUF]
    float2*  tw512 = (float2*)(s_im + 4 * FFTBUF);         // [512]
    __half2* stage = (__half2*)(tw512 + 512);              // [512*17]

    int tid = threadIdx.x;
    int f   = tid >> 6;
    int tt  = tid & 63;
    int col = blockIdx.x;
    int b   = blockIdx.y;

#pragma unroll
    for (int j = 0; j < 2; j++) {
        int idx = tid + 256 * j;
        float ang = -CUDART_PI_F * (float)idx / 256.0f;
        float s, cc; sincosf(ang, &s, &cc);
        tw512[idx] = make_float2(cc, s);
    }

    float* re = s_re + f * FFTBUF;
    float* im = s_im + f * FFTBUF;

#pragma unroll 1
    for (int cc = 0; cc < 4; cc++) {
        int c = cc * 4 + f;
        const float2* in = g_Gr + ((size_t)(b * COILS + c) * NIM) * KG + col;
#pragma unroll
        for (int j = 0; j < 4; j++) {
            int n = tt + 64 * j;
            float2 v = in[(size_t)n * KG];
            int d = PADI(digitrev8(n));
            re[d] = v.x;
            im[d] = v.y;
        }
#pragma unroll
        for (int j = 4; j < 8; j++) {
            int d = PADI(digitrev8(tt + 64 * j));
            re[d] = 0.f;
            im[d] = 0.f;
        }
        __syncthreads();

        fft512_r8(re, im, tw512, tt);   // ends with __syncthreads()

#pragma unroll
        for (int j = 0; j < 8; j++) {
            int n = tt + 64 * j;
            int d = PADI(n);
            stage[n * 17 + c] =
                __floats2half2_rn(clampq(re[d] * GSCALE), clampq(im[d] * GSCALE));
        }
        __syncthreads();   // stage reads of re/im done before next round overwrites
    }

    // Coalesced write: consecutive threads -> consecutive coils (64B segments).
    __half2* out = g_Gft + (size_t)b * KG * KG * COILS + (size_t)col * COILS;
#pragma unroll
    for (int i = 0; i < 32; i++) {
        int idx = i * 256 + tid;      // idx = n*16 + c
        int n   = idx >> 4;
        int c   = idx & 15;
        out[(size_t)n * (KG * COILS) + c] = stage[n * 17 + c];
    }
}

// ---------------------------------------------------------------------------
// Interpolation: 64 points x 4 threads (4 coils each) per block. grid(M/64, B).
// Packed f32x2 FMA accumulation + 3-deep load batching.
// ---------------------------------------------------------------------------
#define PB 64
__global__ __launch_bounds__(256) void interp_kernel(const float* __restrict__ om,
                                                     const float* __restrict__ tab0,
                                                     const float* __restrict__ tab1,
                                                     const float* __restrict__ nshift,
                                                     float* __restrict__ out) {
    __shared__ float2 sc0[PB][JW];
    __shared__ float2 sc1[PB][JW];
    __shared__ int    si0[PB][JW];   // row * KG * COILS
    __shared__ int    si1[PB][JW];   // col * COILS
    __shared__ float2 sph[PB];
    __shared__ float  sout[32 * PB];   // [c*2+comp][p]

    int b  = blockIdx.y;
    int m0 = blockIdx.x * PB;
    int t  = threadIdx.x;

    if (t < PB) {
        int m = m0 + t;
        float om0 = om[((size_t)b * 2 + 0) * MPTS + m];
        float om1 = om[((size_t)b * 2 + 1) * MPTS + m];
        const float S = (float)(KG / (2.0 * 3.14159265358979323846));
        float tm0 = om0 * S;
        float tm1 = om1 * S;
        int koff0 = (int)floorf(tm0 - 3.0f) + 1;
        int koff1 = (int)floorf(tm1 - 3.0f) + 1;
#pragma unroll
        for (int j = 0; j < JW; j++) {
            int g0   = koff0 + j;
            int idx0 = __float2int_rn((tm0 - (float)g0) * 1024.0f) + TCENTER;
            sc0[t][j] = make_float2(tab0[idx0], tab0[TLEN + idx0]);
            si0[t][j] = (g0 & (KG - 1)) * (KG * COILS);
            int g1   = koff1 + j;
            int idx1 = __float2int_rn((tm1 - (float)g1) * 1024.0f) + TCENTER;
            sc1[t][j] = make_float2(tab1[idx1], tab1[TLEN + idx1]);
            si1[t][j] = (g1 & (KG - 1)) * COILS;
        }
        float ph = om0 * nshift[0] + om1 * nshift[1];
        float sp, cp;
        sincosf(ph, &sp, &cp);
        sph[t] = make_float2(cp * GSCALE_I, sp * GSCALE_I);
    }
    __syncthreads();

    int p  = t >> 2;
    int q4 = (t & 3) * 4;   // coil base (4 coils per thread)
    const __half2* G = g_Gft + (size_t)b * KG * KG * COILS + q4;

    unsigned long long acc0 = pk2(0.f, 0.f);
    unsigned long long acc1 = acc0, acc2 = acc0, acc3 = acc0;

#pragma unroll
    for (int a = 0; a < JW; a++) {
        float2 ca   = sc0[p][a];
        int    roff = si0[p][a];
#pragma unroll
        for (int g = 0; g < 2; g++) {
            float4 raw0 = *reinterpret_cast<const float4*>(G + roff + si1[p][g * 3 + 0]);
            float4 raw1 = *reinterpret_cast<const float4*>(G + roff + si1[p][g * 3 + 1]);
            float4 raw2 = *reinterpret_cast<const float4*>(G + roff + si1[p][g * 3 + 2]);
#pragma unroll
            for (int u = 0; u < 3; u++) {
                float4 raw = (u == 0) ? raw0 : (u == 1) ? raw1 : raw2;
                float2 cf  = cmulf(ca, sc1[p][g * 3 + u]);
                unsigned long long cxx = pk2(cf.x, cf.x);
                unsigned long long cyn = pk2(-cf.y, cf.y);
                float2 v0 = __half22float2(*reinterpret_cast<__half2*>(&raw.x));
                float2 v1 = __half22float2(*reinterpret_cast<__half2*>(&raw.y));
                float2 v2 = __half22float2(*reinterpret_cast<__half2*>(&raw.z));
                float2 v3 = __half22float2(*reinterpret_cast<__half2*>(&raw.w));
                fma2(acc0, pk2(v0.x, v0.y), cxx);
                fma2(acc0, pk2(v0.y, v0.x), cyn);
                fma2(acc1, pk2(v1.x, v1.y), cxx);
                fma2(acc1, pk2(v1.y, v1.x), cyn);
                fma2(acc2, pk2(v2.x, v2.y), cxx);
                fma2(acc2, pk2(v2.y, v2.x), cyn);
                fma2(acc3, pk2(v3.x, v3.y), cxx);
                fma2(acc3, pk2(v3.y, v3.x), cyn);
            }
        }
    }

    float2 a0, a1, a2, a3;
    upk2(a0.x, a0.y, acc0);
    upk2(a1.x, a1.y, acc1);
    upk2(a2.x, a2.y, acc2);
    upk2(a3.x, a3.y, acc3);

    float2 ph = sph[p];
    float2 r0 = cmulf(a0, ph);
    float2 r1 = cmulf(a1, ph);
    float2 r2 = cmulf(a2, ph);
    float2 r3 = cmulf(a3, ph);

    sout[((q4 + 0) * 2 + 0) * PB + p] = r0.x;  sout[((q4 + 0) * 2 + 1) * PB + p] = r0.y;
    sout[((q4 + 1) * 2 + 0) * PB + p] = r1.x;  sout[((q4 + 1) * 2 + 1) * PB + p] = r1.y;
    sout[((q4 + 2) * 2 + 0) * PB + p] = r2.x;  sout[((q4 + 2) * 2 + 1) * PB + p] = r2.y;
    sout[((q4 + 3) * 2 + 0) * PB + p] = r3.x;  sout[((q4 + 3) * 2 + 1) * PB + p] = r3.y;
    __syncthreads();

    float* outp = out + (size_t)b * 2 * COILS * MPTS + m0;
#pragma unroll
    for (int i = 0; i < 8; i++) {
        int idx = i * 256 + t;
        int cr  = idx >> 6;       // c*2+comp
        int m   = idx & 63;
        outp[(size_t)cr * MPTS + m] = sout[idx];
    }
}

extern "C" void kernel_launch(void* const* d_in, const int* in_sizes, int n_in,
                              void* d_out, int out_size) {
    (void)in_sizes; (void)n_in; (void)out_size;
    const float* x      = (const float*)d_in[0];
    const float* om     = (const float*)d_in[1];
    const float* sc     = (const float*)d_in[2];
    const float* tab0   = (const float*)d_in[3];
    const float* tab1   = (const float*)d_in[4];
    const float* nshift = (const float*)d_in[5];
    float* out          = (float*)d_out;

    cudaFuncSetAttribute(pass2_colfft,
                         cudaFuncAttributeMaxDynamicSharedMemorySize, P2_SMEM);

    dim3 g1(NIM / 4, BATCH * COILS);
    pass1_rowfft<<<g1, 256>>>(x, sc);

    dim3 g2(KG, BATCH);
    pass2_colfft<<<g2, 256, P2_SMEM>>>();

    dim3 g3(MPTS / PB, BATCH);
    interp_kernel<<<g3, 256>>>(om, tab0, tab1, nshift, out);
}

// round 11
// speedup vs baseline: 2.6683x; 1.0887x over previous
#include <cuda_runtime.h>
#include <cuda_fp16.h>
#include <math_constants.h>

#define BATCH  2
#define COILS  16
#define NIM    256
#define KG     512
#define JW     6
#define TCENTER 3072
#define TLEN   6145
#define MPTS   409600
#define GSCALE   0x1p-34f
#define GSCALE_I 0x1p34f

#define PADI(i) ((i) + ((i) >> 5))   // bank-conflict padding; max 511 -> 526
#define FFTBUF 536                   // 8 mod 32 -> transpose-phase conflict-free

// Scratch: TRANSPOSED row-FFT output (B,C, col*256+row) fp32 and
// coil-innermost grid (B, 512*512, C) fp16
static __device__ __align__(256) float2  g_GrT[(size_t)BATCH*COILS*NIM*KG];
static __device__ __align__(256) __half2 g_Gft[(size_t)BATCH*KG*KG*COILS];

__device__ __forceinline__ float2 cmulf(float2 a, float2 b) {
    return make_float2(a.x*b.x - a.y*b.y, a.x*b.y + a.y*b.x);
}

__device__ __forceinline__ float clampq(float v) {
    return fminf(fmaxf(v, -60000.0f), 60000.0f);
}

// ---- packed f32x2 helpers (sm_103a) ----
__device__ __forceinline__ unsigned long long pk2(float lo, float hi) {
    unsigned long long r;
    asm("mov.b64 %0, {%1, %2};" : "=l"(r) : "f"(lo), "f"(hi));
    return r;
}
__device__ __forceinline__ void upk2(float& lo, float& hi, unsigned long long v) {
    asm("mov.b64 {%0, %1}, %2;" : "=f"(lo), "=f"(hi) : "l"(v));
}
__device__ __forceinline__ void fma2(unsigned long long& d,
                                     unsigned long long a,
                                     unsigned long long b) {
    asm("fma.rn.f32x2 %0, %1, %2, %0;" : "+l"(d) : "l"(a), "l"(b));
}

// ---------------------------------------------------------------------------
// Straight-line 8-point DFT, natural-order in/out. X[k] = sum_i x[i] w8^{ik}.
// ---------------------------------------------------------------------------
__device__ __forceinline__ void dft8(float2 x[8]) {
    const float RH = 0.70710678118654752f;
    float2 ec0 = make_float2(x[0].x + x[4].x, x[0].y + x[4].y);
    float2 ec1 = make_float2(x[0].x - x[4].x, x[0].y - x[4].y);
    float2 ec2 = make_float2(x[2].x + x[6].x, x[2].y + x[6].y);
    float2 ec3 = make_float2(x[2].x - x[6].x, x[2].y - x[6].y);
    float2 E0 = make_float2(ec0.x + ec2.x, ec0.y + ec2.y);
    float2 E2 = make_float2(ec0.x - ec2.x, ec0.y - ec2.y);
    float2 E1 = make_float2(ec1.x + ec3.y, ec1.y - ec3.x);
    float2 E3 = make_float2(ec1.x - ec3.y, ec1.y + ec3.x);
    float2 oc0 = make_float2(x[1].x + x[5].x, x[1].y + x[5].y);
    float2 oc1 = make_float2(x[1].x - x[5].x, x[1].y - x[5].y);
    float2 oc2 = make_float2(x[3].x + x[7].x, x[3].y + x[7].y);
    float2 oc3 = make_float2(x[3].x - x[7].x, x[3].y - x[7].y);
    float2 O0 = make_float2(oc0.x + oc2.x, oc0.y + oc2.y);
    float2 O2 = make_float2(oc0.x - oc2.x, oc0.y - oc2.y);
    float2 O1 = make_float2(oc1.x + oc3.y, oc1.y - oc3.x);
    float2 O3 = make_float2(oc1.x - oc3.y, oc1.y + oc3.x);
    float2 t1 = make_float2(RH * (O1.x + O1.y), RH * (O1.y - O1.x));
    float2 t2 = make_float2(O2.y, -O2.x);
    float2 t3 = make_float2(RH * (O3.y - O3.x), -RH * (O3.x + O3.y));
    x[0] = make_float2(E0.x + O0.x, E0.y + O0.y);
    x[4] = make_float2(E0.x - O0.x, E0.y - O0.y);
    x[1] = make_float2(E1.x + t1.x, E1.y + t1.y);
    x[5] = make_float2(E1.x - t1.x, E1.y - t1.y);
    x[2] = make_float2(E2.x + t2.x, E2.y + t2.y);
    x[6] = make_float2(E2.x - t2.x, E2.y - t2.y);
    x[3] = make_float2(E3.x + t3.x, E3.y + t3.y);
    x[7] = make_float2(E3.x - t3.x, E3.y - t3.y);
}

// 512-pt FFT as 3 radix-8 stages, 64 threads (tt in [0,64)).
// Input must be scattered to PADI(digitrev8(n)); output natural at PADI(n).
// tw512[j] = exp(-2*pi*i*j/512). Caller syncs before entry.
__device__ __forceinline__ void fft512_r8(float* re, float* im,
                                          const float2* tw512, int tt) {
    float2 x[8];
    {
        int base = 8 * tt;
#pragma unroll
        for (int i = 0; i < 8; i++) {
            int a = PADI(base + i);
            x[i] = make_float2(re[a], im[a]);
        }
        dft8(x);
#pragma unroll
        for (int i = 0; i < 8; i++) {
            int a = PADI(base + i);
            re[a] = x[i].x; im[a] = x[i].y;
        }
    }
    __syncthreads();
    {
        int g = tt & 7, r = tt >> 3;
        int base = 64 * g + r;
#pragma unroll
        for (int i = 0; i < 8; i++) {
            int a = PADI(base + 8 * i);
            x[i] = make_float2(re[a], im[a]);
        }
#pragma unroll
        for (int i = 1; i < 8; i++)
            x[i] = cmulf(x[i], tw512[(8 * r * i) & 511]);
        dft8(x);
#pragma unroll
        for (int i = 0; i < 8; i++) {
            int a = PADI(base + 8 * i);
            re[a] = x[i].x; im[a] = x[i].y;
        }
    }
    __syncthreads();
    {
#pragma unroll
        for (int i = 0; i < 8; i++) {
            int a = PADI(tt + 64 * i);
            x[i] = make_float2(re[a], im[a]);
        }
#pragma unroll
        for (int i = 1; i < 8; i++)
            x[i] = cmulf(x[i], tw512[(tt * i) & 511]);
        dft8(x);
#pragma unroll
        for (int i = 0; i < 8; i++) {
            int a = PADI(tt + 64 * i);
            re[a] = x[i].x; im[a] = x[i].y;
        }
    }
    __syncthreads();
}

__device__ __forceinline__ int digitrev8(int n) {
    return ((n & 7) << 6) | (((n >> 3) & 7) << 3) | (n >> 6);
}

// ---------------------------------------------------------------------------
// Pass 1: apodize + row FFT + TRANSPOSED store. 4 rows per 256-thread block.
// grid(64, B*C). g_GrT[bc][col*256 + row].
// ---------------------------------------------------------------------------
__global__ __launch_bounds__(256) void pass1_rowfft(const float* __restrict__ x,
                                                    const float* __restrict__ sc) {
    __shared__ float  s_re[4][FFTBUF];
    __shared__ float  s_im[4][FFTBUF];
    __shared__ float2 tw512[512];
    int tid = threadIdx.x;
    int f   = tid >> 6;
    int tt  = tid & 63;
    int r0  = blockIdx.x * 4;
    int r   = r0 + f;
    int bc  = blockIdx.y;

#pragma unroll
    for (int j = 0; j < 2; j++) {
        int idx = tid + 256 * j;
        float ang = -CUDART_PI_F * (float)idx / 256.0f;   // -2*pi*idx/512
        float s, c; sincosf(ang, &s, &c);
        tw512[idx] = make_float2(c, s);
    }

    float* re = s_re[f];
    float* im = s_im[f];

    const float* xr  = x  + ((size_t)bc * 2 + 0) * (NIM * NIM) + (size_t)r * NIM;
    const float* xi  = x  + ((size_t)bc * 2 + 1) * (NIM * NIM) + (size_t)r * NIM;
    const float* scr = sc + (size_t)r * NIM;
    const float* sci = sc + (size_t)NIM * NIM + (size_t)r * NIM;

#pragma unroll
    for (int j = 0; j < 4; j++) {
        int n = tt + 64 * j;
        float a = xr[n], b = xi[n], cr = scr[n], ci = sci[n];
        int d = PADI(digitrev8(n));
        re[d] = a * cr - b * ci;
        im[d] = a * ci + b * cr;
    }
#pragma unroll
    for (int j = 4; j < 8; j++) {
        int d = PADI(digitrev8(tt + 64 * j));
        re[d] = 0.f;
        im[d] = 0.f;
    }
    __syncthreads();

    fft512_r8(re, im, tw512, tt);   // ends with __syncthreads()

    // Transposed store: 4 consecutive rows of one column = contiguous 32B.
    float2* outT = g_GrT + (size_t)bc * NIM * KG;
#pragma unroll
    for (int j = 0; j < 8; j++) {
        int idx = j * 256 + tid;     // 0..2047 = 512 cols x 4 rows
        int col = idx >> 2;
        int r4  = idx & 3;
        int d   = PADI(col);
        outT[(size_t)col * NIM + r0 + r4] = make_float2(s_re[r4][d], s_im[r4][d]);
    }
}

// ---------------------------------------------------------------------------
// Pass 2: column FFT for ALL 16 coils of one column per block, staged in smem,
// then one fully-coalesced fp16 write phase. grid(KG, BATCH), 256 threads.
// 4 concurrent radix-8 FFTs (f = tid>>6) x 4 rounds. Reads are now contiguous.
// ---------------------------------------------------------------------------
#define P2_SMEM (4 * FFTBUF * 2 * 4 + 512 * 8 + 512 * 17 * 4)
__global__ __launch_bounds__(256) void pass2_colfft() {
    extern __shared__ char smem2[];
    float*   s_re  = (float*)smem2;                        // [4][FFTBUF]
    float*   s_im  = s_re + 4 * FFTBUF;                    // [4][FFTBUF]
    float2*  tw512 = (float2*)(s_im + 4 * FFTBUF);         // [512]
    __half2* stage = (__half2*)(tw512 + 512);              // [512*17]

    int tid = threadIdx.x;
    int f   = tid >> 6;
    int tt  = tid & 63;
    int col = blockIdx.x;
    int b   = blockIdx.y;

#pragma unroll
    for (int j = 0; j < 2; j++) {
        int idx = tid + 256 * j;
        float ang = -CUDART_PI_F * (float)idx / 256.0f;
        float s, cc; sincosf(ang, &s, &cc);
        tw512[idx] = make_float2(cc, s);
    }

    float* re = s_re + f * FFTBUF;
    float* im = s_im + f * FFTBUF;

#pragma unroll 1
    for (int cc = 0; cc < 4; cc++) {
        int c = cc * 4 + f;
        // contiguous 256-row column slice
        const float2* inT = g_GrT + ((size_t)(b * COILS + c) * NIM) * KG
                          + (size_t)col * NIM;
#pragma unroll
        for (int j = 0; j < 4; j++) {
            int n = tt + 64 * j;
            float2 v = inT[n];
            int d = PADI(digitrev8(n));
            re[d] = v.x;
            im[d] = v.y;
        }
#pragma unroll
        for (int j = 4; j < 8; j++) {
            int d = PADI(digitrev8(tt + 64 * j));
            re[d] = 0.f;
            im[d] = 0.f;
        }
        __syncthreads();

        fft512_r8(re, im, tw512, tt);   // ends with __syncthreads()

#pragma unroll
        for (int j = 0; j < 8; j++) {
            int n = tt + 64 * j;
            int d = PADI(n);
            stage[n * 17 + c] =
                __floats2half2_rn(clampq(re[d] * GSCALE), clampq(im[d] * GSCALE));
        }
        __syncthreads();   // stage reads of re/im done before next round overwrites
    }

    // Coalesced write: consecutive threads -> consecutive coils (64B segments).
    __half2* out = g_Gft + (size_t)b * KG * KG * COILS + (size_t)col * COILS;
#pragma unroll
    for (int i = 0; i < 32; i++) {
        int idx = i * 256 + tid;      // idx = n*16 + c
        int n   = idx >> 4;
        int c   = idx & 15;
        out[(size_t)n * (KG * COILS) + c] = stage[n * 17 + c];
    }
}

// ---------------------------------------------------------------------------
// Interpolation: 64 points x 4 threads (4 coils each) per block. grid(M/64, B).
// Packed f32x2 FMA accumulation + 3-deep load batching.
// ---------------------------------------------------------------------------
#define PB 64
__global__ __launch_bounds__(256) void interp_kernel(const float* __restrict__ om,
                                                     const float* __restrict__ tab0,
                                                     const float* __restrict__ tab1,
                                                     const float* __restrict__ nshift,
                                                     float* __restrict__ out) {
    __shared__ float2 sc0[PB][JW];
    __shared__ float2 sc1[PB][JW];
    __shared__ int    si0[PB][JW];   // row * KG * COILS
    __shared__ int    si1[PB][JW];   // col * COILS
    __shared__ float2 sph[PB];
    __shared__ float  sout[32 * PB];   // [c*2+comp][p]

    int b  = blockIdx.y;
    int m0 = blockIdx.x * PB;
    int t  = threadIdx.x;

    if (t < PB) {
        int m = m0 + t;
        float om0 = om[((size_t)b * 2 + 0) * MPTS + m];
        float om1 = om[((size_t)b * 2 + 1) * MPTS + m];
        const float S = (float)(KG / (2.0 * 3.14159265358979323846));
        float tm0 = om0 * S;
        float tm1 = om1 * S;
        int koff0 = (int)floorf(tm0 - 3.0f) + 1;
        int koff1 = (int)floorf(tm1 - 3.0f) + 1;
#pragma unroll
        for (int j = 0; j < JW; j++) {
            int g0   = koff0 + j;
            int idx0 = __float2int_rn((tm0 - (float)g0) * 1024.0f) + TCENTER;
            sc0[t][j] = make_float2(tab0[idx0], tab0[TLEN + idx0]);
            si0[t][j] = (g0 & (KG - 1)) * (KG * COILS);
            int g1   = koff1 + j;
            int idx1 = __float2int_rn((tm1 - (float)g1) * 1024.0f) + TCENTER;
            sc1[t][j] = make_float2(tab1[idx1], tab1[TLEN + idx1]);
            si1[t][j] = (g1 & (KG - 1)) * COILS;
        }
        float ph = om0 * nshift[0] + om1 * nshift[1];
        float sp, cp;
        sincosf(ph, &sp, &cp);
        sph[t] = make_float2(cp * GSCALE_I, sp * GSCALE_I);
    }
    __syncthreads();

    int p  = t >> 2;
    int q4 = (t & 3) * 4;   // coil base (4 coils per thread)
    const __half2* G = g_Gft + (size_t)b * KG * KG * COILS + q4;

    unsigned long long acc0 = pk2(0.f, 0.f);
    unsigned long long acc1 = acc0, acc2 = acc0, acc3 = acc0;

#pragma unroll
    for (int a = 0; a < JW; a++) {
        float2 ca   = sc0[p][a];
        int    roff = si0[p][a];
#pragma unroll
        for (int g = 0; g < 2; g++) {
            float4 raw0 = *reinterpret_cast<const float4*>(G + roff + si1[p][g * 3 + 0]);
            float4 raw1 = *reinterpret_cast<const float4*>(G + roff + si1[p][g * 3 + 1]);
            float4 raw2 = *reinterpret_cast<const float4*>(G + roff + si1[p][g * 3 + 2]);
#pragma unroll
            for (int u = 0; u < 3; u++) {
                float4 raw = (u == 0) ? raw0 : (u == 1) ? raw1 : raw2;
                float2 cf  = cmulf(ca, sc1[p][g * 3 + u]);
                unsigned long long cxx = pk2(cf.x, cf.x);
                unsigned long long cyn = pk2(-cf.y, cf.y);
                float2 v0 = __half22float2(*reinterpret_cast<__half2*>(&raw.x));
                float2 v1 = __half22float2(*reinterpret_cast<__half2*>(&raw.y));
                float2 v2 = __half22float2(*reinterpret_cast<__half2*>(&raw.z));
                float2 v3 = __half22float2(*reinterpret_cast<__half2*>(&raw.w));
                fma2(acc0, pk2(v0.x, v0.y), cxx);
                fma2(acc0, pk2(v0.y, v0.x), cyn);
                fma2(acc1, pk2(v1.x, v1.y), cxx);
                fma2(acc1, pk2(v1.y, v1.x), cyn);
                fma2(acc2, pk2(v2.x, v2.y), cxx);
                fma2(acc2, pk2(v2.y, v2.x), cyn);
                fma2(acc3, pk2(v3.x, v3.y), cxx);
                fma2(acc3, pk2(v3.y, v3.x), cyn);
            }
        }
    }

    float2 a0, a1, a2, a3;
    upk2(a0.x, a0.y, acc0);
    upk2(a1.x, a1.y, acc1);
    upk2(a2.x, a2.y, acc2);
    upk2(a3.x, a3.y, acc3);

    float2 ph = sph[p];
    float2 r0 = cmulf(a0, ph);
    float2 r1 = cmulf(a1, ph);
    float2 r2 = cmulf(a2, ph);
    float2 r3 = cmulf(a3, ph);

    sout[((q4 + 0) * 2 + 0) * PB + p] = r0.x;  sout[((q4 + 0) * 2 + 1) * PB + p] = r0.y;
    sout[((q4 + 1) * 2 + 0) * PB + p] = r1.x;  sout[((q4 + 1) * 2 + 1) * PB + p] = r1.y;
    sout[((q4 + 2) * 2 + 0) * PB + p] = r2.x;  sout[((q4 + 2) * 2 + 1) * PB + p] = r2.y;
    sout[((q4 + 3) * 2 + 0) * PB + p] = r3.x;  sout[((q4 + 3) * 2 + 1) * PB + p] = r3.y;
    __syncthreads();

    float* outp = out + (size_t)b * 2 * COILS * MPTS + m0;
#pragma unroll
    for (int i = 0; i < 8; i++) {
        int idx = i * 256 + t;
        int cr  = idx >> 6;       // c*2+comp
        int m   = idx & 63;
        outp[(size_t)cr * MPTS + m] = sout[idx];
    }
}

extern "C" void kernel_launch(void* const* d_in, const int* in_sizes, int n_in,
                              void* d_out, int out_size) {
    (void)in_sizes; (void)n_in; (void)out_size;
    const float* x      = (const float*)d_in[0];
    const float* om     = (const float*)d_in[1];
    const float* sc     = (const float*)d_in[2];
    const float* tab0   = (const float*)d_in[3];
    const float* tab1   = (const float*)d_in[4];
    const float* nshift = (const float*)d_in[5];
    float* out          = (float*)d_out;

    cudaFuncSetAttribute(pass2_colfft,
                         cudaFuncAttributeMaxDynamicSharedMemorySize, P2_SMEM);

    dim3 g1(NIM / 4, BATCH * COILS);
    pass1_rowfft<<<g1, 256>>>(x, sc);

    dim3 g2(KG, BATCH);
    pass2_colfft<<<g2, 256, P2_SMEM>>>();

    dim3 g3(MPTS / PB, BATCH);
    interp_kernel<<<g3, 256>>>(om, tab0, tab1, nshift, out);
}